// round 1
// baseline (speedup 1.0000x reference)
#include <cuda_runtime.h>
#include <math.h>

#define Bb 4
#define Ll 2048
#define Dd 1024
#define Hh 16
#define HD 64
#define MROWS (Bb*Ll)        // 8192
#define NQKUV (4*Dd)         // 4096

// Scratch (static device allocations are allowed; cudaMalloc is not)
__device__ float g_qkuv[(size_t)MROWS * NQKUV];   // 128 MB: silu(x @ Wqkuv), natural layout
__device__ float g_attn[(size_t)Bb*Hh*Ll*HD];     // 32 MB: attention output (B,H,L,d)
__device__ float g_flat[(size_t)MROWS * Dd];      // 32 MB: LN+gate output (B,L,D)

__device__ __forceinline__ float silu_f(float x) { return x / (1.0f + expf(-x)); }

// ---------------------------------------------------------------------------
// SGEMM: C[M,N] = (silu?)(A[M,K] @ W[K,N]); all dims multiples of tile sizes.
// 128x128x16 tile, 256 threads, 8x8 per-thread, float4 everywhere.
// ---------------------------------------------------------------------------
template<bool SILU>
__global__ __launch_bounds__(256) void sgemm_kernel(
    const float* __restrict__ A, const float* __restrict__ W,
    float* __restrict__ C, int Mdim, int Ndim, int Kdim)
{
    const int BK = 16;
    __shared__ float As[BK][132];   // transposed, padded
    __shared__ float Bs[BK][128];
    const int tid = threadIdx.x;
    const int tr = tid >> 4, tc = tid & 15;
    const int m0 = blockIdx.y * 128, n0 = blockIdx.x * 128;

    float acc[8][8] = {};

    for (int k0 = 0; k0 < Kdim; k0 += BK) {
        #pragma unroll
        for (int i = 0; i < 2; i++) {               // A tile: 128x16 = 512 float4
            int f = tid + i * 256;
            int ar = f >> 2, ac4 = f & 3;
            float4 v = *(const float4*)(A + (size_t)(m0 + ar) * Kdim + k0 + ac4 * 4);
            As[ac4*4+0][ar] = v.x; As[ac4*4+1][ar] = v.y;
            As[ac4*4+2][ar] = v.z; As[ac4*4+3][ar] = v.w;
        }
        #pragma unroll
        for (int i = 0; i < 2; i++) {               // B tile: 16x128 = 512 float4
            int f = tid + i * 256;
            int br = f >> 5, bc4 = f & 31;
            *(float4*)&Bs[br][bc4*4] =
                *(const float4*)(W + (size_t)(k0 + br) * Ndim + n0 + bc4 * 4);
        }
        __syncthreads();
        #pragma unroll
        for (int k = 0; k < BK; k++) {
            float ra[8], rb[8];
            *(float4*)&ra[0] = *(float4*)&As[k][tr*8];
            *(float4*)&ra[4] = *(float4*)&As[k][tr*8+4];
            *(float4*)&rb[0] = *(float4*)&Bs[k][tc*8];
            *(float4*)&rb[4] = *(float4*)&Bs[k][tc*8+4];
            #pragma unroll
            for (int i = 0; i < 8; i++)
                #pragma unroll
                for (int j = 0; j < 8; j++)
                    acc[i][j] += ra[i] * rb[j];
        }
        __syncthreads();
    }

    #pragma unroll
    for (int i = 0; i < 8; i++) {
        float vals[8];
        #pragma unroll
        for (int j = 0; j < 8; j++)
            vals[j] = SILU ? silu_f(acc[i][j]) : acc[i][j];
        float* row = C + (size_t)(m0 + tr*8 + i) * Ndim + n0 + tc*8;
        *(float4*)row       = *(float4*)&vals[0];
        *(float4*)(row + 4) = *(float4*)&vals[4];
    }
}

// ---------------------------------------------------------------------------
// RoPE in-place on q and k slices of g_qkuv. One thread per (b,l,h,i<32) pair.
// ---------------------------------------------------------------------------
__global__ void rope_kernel(float* __restrict__ qkuv)
{
    int tid = blockIdx.x * blockDim.x + threadIdx.x;   // B*L*H*32 = 2^22
    int i = tid & 31;
    int h = (tid >> 5) & (Hh - 1);
    int l = (tid >> 9) & (Ll - 1);
    int b = tid >> 20;
    // inv_freq = 10000^(-i/32) = exp(-i * ln(10000)/32)
    float inv_freq = expf(-(float)i * 0.28782313662425583f);
    float theta = (float)l * inv_freq;
    float c = cosf(theta), s = sinf(theta);
    float* base = qkuv + ((size_t)(b * Ll + l)) * NQKUV + h * HD;
    float q0 = base[i], q1 = base[i + 32];
    base[i]      = q0 * c - q1 * s;
    base[i + 32] = q1 * c + q0 * s;
    float* kb = base + Dd;
    float k0 = kb[i], k1 = kb[i + 32];
    kb[i]      = k0 * c - k1 * s;
    kb[i + 32] = k1 * c + k0 * s;
}

// ---------------------------------------------------------------------------
// Fused attention: per (b,h, 128-row q tile), sweep all keys in 128-key tiles.
// S = silu(qk^T/8 + cmask*cbias) * attn_mask computed tile-by-tile in smem,
// immediately consumed by S @ V. No global score buffer.
// ---------------------------------------------------------------------------
#define PADQ 132
#define PADS 129
__global__ __launch_bounds__(256) void attn_kernel(
    const float* __restrict__ qkuv, const float* __restrict__ attn_mask,
    const float* __restrict__ cmask, const float* __restrict__ cbias,
    float* __restrict__ out)
{
    extern __shared__ float sm[];
    float* qsT = sm;                       // [64][PADQ]  q transposed (dd, l)
    float* ksT = qsT + 64 * PADQ;          // [64][PADQ]  k transposed (dd, m)
    float* vs  = ksT + 64 * PADQ;          // [128][64]   v natural (m, dd)
    float* ssT = vs + 128 * 64;            // [128][PADS] S transposed (m, l)

    const int tid = threadIdx.x;
    const int tr = tid >> 4, tc = tid & 15;
    const int b = blockIdx.z, h = blockIdx.y;
    const int l0 = blockIdx.x * 128;
    const float cb = cbias[h];

    const float* qbase = qkuv + (size_t)(b * Ll) * NQKUV + h * HD;
    const float* kbase = qbase + Dd;
    const float* vbase = qbase + 2 * Dd;

    // load q tile (128 x 64) transposed
    #pragma unroll
    for (int i = 0; i < 8; i++) {
        int f = tid + i * 256;             // 2048 float4
        int l = f >> 4, c4 = f & 15;
        float4 v = *(const float4*)(qbase + (size_t)(l0 + l) * NQKUV + c4 * 4);
        qsT[(c4*4+0)*PADQ + l] = v.x;
        qsT[(c4*4+1)*PADQ + l] = v.y;
        qsT[(c4*4+2)*PADQ + l] = v.z;
        qsT[(c4*4+3)*PADQ + l] = v.w;
    }

    float accd[8][4] = {};

    for (int mt = 0; mt < Ll / 128; mt++) {
        const int m0 = mt * 128;
        #pragma unroll
        for (int i = 0; i < 8; i++) {      // load k (transposed) + v (natural)
            int f = tid + i * 256;
            int m = f >> 4, c4 = f & 15;
            float4 kv = *(const float4*)(kbase + (size_t)(m0 + m) * NQKUV + c4 * 4);
            ksT[(c4*4+0)*PADQ + m] = kv.x;
            ksT[(c4*4+1)*PADQ + m] = kv.y;
            ksT[(c4*4+2)*PADQ + m] = kv.z;
            ksT[(c4*4+3)*PADQ + m] = kv.w;
            *(float4*)&vs[m * 64 + c4 * 4] =
                *(const float4*)(vbase + (size_t)(m0 + m) * NQKUV + c4 * 4);
        }
        __syncthreads();

        // GEMM1: S[l, m] over dd=0..63
        float sacc[8][8] = {};
        #pragma unroll 4
        for (int k = 0; k < 64; k++) {
            float ra[8], rb[8];
            *(float4*)&ra[0] = *(float4*)&qsT[k*PADQ + tr*8];
            *(float4*)&ra[4] = *(float4*)&qsT[k*PADQ + tr*8 + 4];
            *(float4*)&rb[0] = *(float4*)&ksT[k*PADQ + tc*8];
            *(float4*)&rb[4] = *(float4*)&ksT[k*PADQ + tc*8 + 4];
            #pragma unroll
            for (int i = 0; i < 8; i++)
                #pragma unroll
                for (int j = 0; j < 8; j++)
                    sacc[i][j] += ra[i] * rb[j];
        }

        // epilogue: scale, conversion bias, SiLU, multiplicative mask
        float cmv[8];
        *(float4*)&cmv[0] = *(const float4*)(cmask + b * Ll + m0 + tc*8);
        *(float4*)&cmv[4] = *(const float4*)(cmask + b * Ll + m0 + tc*8 + 4);
        #pragma unroll
        for (int i = 0; i < 8; i++) {
            int lg = l0 + tr*8 + i;
            const float* mrow = attn_mask + ((size_t)b * Ll + lg) * Ll + m0 + tc*8;
            float4 mk0 = *(const float4*)mrow;
            float4 mk1 = *(const float4*)(mrow + 4);
            float mk[8] = {mk0.x, mk0.y, mk0.z, mk0.w, mk1.x, mk1.y, mk1.z, mk1.w};
            #pragma unroll
            for (int j = 0; j < 8; j++) {
                float xv = sacc[i][j] * 0.125f + cmv[j] * cb;
                sacc[i][j] = (xv / (1.0f + expf(-xv))) * mk[j];
            }
        }

        // store S transposed (m, l)
        #pragma unroll
        for (int j = 0; j < 8; j++)
            #pragma unroll
            for (int i = 0; i < 8; i++)
                ssT[(tc*8 + j) * PADS + tr*8 + i] = sacc[i][j];
        __syncthreads();

        // GEMM2: accd[l, dd] += S[l, m] * v[m, dd] over m=0..127
        #pragma unroll 4
        for (int k = 0; k < 128; k++) {
            float ra[8];
            float4 rb = *(float4*)&vs[k * 64 + tc * 4];
            #pragma unroll
            for (int i = 0; i < 8; i++) ra[i] = ssT[k * PADS + tr*8 + i];
            #pragma unroll
            for (int i = 0; i < 8; i++) {
                accd[i][0] += ra[i] * rb.x;
                accd[i][1] += ra[i] * rb.y;
                accd[i][2] += ra[i] * rb.z;
                accd[i][3] += ra[i] * rb.w;
            }
        }
        __syncthreads();
    }

    float* obase = out + ((size_t)(b * Hh + h) * Ll + l0) * HD;
    #pragma unroll
    for (int i = 0; i < 8; i++)
        *(float4*)&obase[(tr*8 + i) * HD + tc * 4] = *(float4*)&accd[i][0];
}

// ---------------------------------------------------------------------------
// LayerNorm over head_dim (64) + SiLU-gate by u, write (B,L,D) layout.
// One warp per (b,h,l) row.
// ---------------------------------------------------------------------------
__global__ void ln_gate_kernel(
    const float* __restrict__ attn, const float* __restrict__ qkuv,
    const float* __restrict__ gamma, const float* __restrict__ beta,
    float* __restrict__ flat)
{
    int warp = (blockIdx.x * blockDim.x + threadIdx.x) >> 5;
    int lane = threadIdx.x & 31;
    int l = warp & (Ll - 1);
    int h = (warp >> 11) & (Hh - 1);
    int b = warp >> 15;
    const float* row = attn + (size_t)warp * HD;
    float v0 = row[lane], v1 = row[lane + 32];
    float s = v0 + v1, sq = v0 * v0 + v1 * v1;
    #pragma unroll
    for (int o = 16; o > 0; o >>= 1) {
        s  += __shfl_xor_sync(0xFFFFFFFFu, s,  o);
        sq += __shfl_xor_sync(0xFFFFFFFFu, sq, o);
    }
    float mu = s * (1.0f / 64.0f);
    float var = sq * (1.0f / 64.0f) - mu * mu;
    float rstd = rsqrtf(var + 1e-5f);
    const float* ub = qkuv + ((size_t)(b * Ll + l)) * NQKUV + 3 * Dd + h * HD;
    float* ob = flat + ((size_t)(b * Ll + l)) * Dd + h * HD;
    ob[lane]      = ((v0 - mu) * rstd * gamma[lane]      + beta[lane])      * ub[lane];
    ob[lane + 32] = ((v1 - mu) * rstd * gamma[lane + 32] + beta[lane + 32]) * ub[lane + 32];
}

// ---------------------------------------------------------------------------
extern "C" void kernel_launch(void* const* d_in, const int* in_sizes, int n_in,
                              void* d_out, int out_size)
{
    // Resolve inputs by element count (robust to ordering); two 64-element
    // inputs (gamma then beta) are taken in encounter order.
    const float *x = nullptr, *attn_mask = nullptr, *cmask = nullptr;
    const float *Wqkuv = nullptr, *Wout = nullptr;
    const float *gamma = nullptr, *beta = nullptr, *cbias = nullptr;
    for (int i = 0; i < n_in; i++) {
        const float* p = (const float*)d_in[i];
        switch (in_sizes[i]) {
            case MROWS * Dd:        x = p; break;          // 8388608
            case Bb * Ll * Ll:      attn_mask = p; break;  // 16777216
            case Bb * Ll:           cmask = p; break;      // 8192
            case Dd * NQKUV:        Wqkuv = p; break;      // 4194304
            case Dd * Dd:           Wout = p; break;       // 1048576
            case HD:                if (!gamma) gamma = p; else beta = p; break;
            case Hh:                cbias = p; break;
            default: break;
        }
    }
    float* out = (float*)d_out;

    float *qkuv, *attn, *flat;
    cudaGetSymbolAddress((void**)&qkuv, g_qkuv);
    cudaGetSymbolAddress((void**)&attn, g_attn);
    cudaGetSymbolAddress((void**)&flat, g_flat);

    // Fused attention needs >48KB dynamic smem
    const int ATTN_SMEM = (64 * PADQ * 2 + 128 * 64 + 128 * PADS) * (int)sizeof(float);
    cudaFuncSetAttribute(attn_kernel, cudaFuncAttributeMaxDynamicSharedMemorySize, ATTN_SMEM);

    // 1) qkuv = silu(x @ Wqkuv)
    sgemm_kernel<true><<<dim3(NQKUV / 128, MROWS / 128), 256>>>(
        x, Wqkuv, qkuv, MROWS, NQKUV, Dd);

    // 2) RoPE on q, k (in place)
    rope_kernel<<<(Bb * Ll * Hh * 32) / 256, 256>>>(qkuv);

    // 3) fused scores + SiLU + mask + S@V
    attn_kernel<<<dim3(Ll / 128, Hh, Bb), 256, ATTN_SMEM>>>(
        qkuv, attn_mask, cmask, cbias, attn);

    // 4) LayerNorm(d) + u-gate, reshape to (B,L,D)
    ln_gate_kernel<<<(Bb * Hh * Ll * 32) / 256, 256>>>(attn, qkuv, gamma, beta, flat);

    // 5) out = flat @ Wout
    sgemm_kernel<false><<<dim3(Dd / 128, MROWS / 128), 256>>>(
        flat, Wout, out, MROWS, Dd, Dd);
}

// round 3
// speedup vs baseline: 1.3761x; 1.3761x over previous
#include <cuda_runtime.h>
#include <cuda_bf16.h>
#include <math.h>
#include <stdint.h>

#define Bb 4
#define Ll 2048
#define Dd 1024
#define Hh 16
#define HD 64
#define MROWS (Bb*Ll)        // 8192
#define NQKUV (4*Dd)         // 4096
#define KDIM  Dd             // 1024

// ---------------- scratch (device globals; no cudaMalloc allowed) ----------
__device__ float g_qkuv[(size_t)MROWS * NQKUV];                 // 128 MB
__device__ float g_attn[(size_t)Bb*Hh*Ll*HD];                   // 32 MB
__device__ __align__(256) __nv_bfloat16 g_xh[(size_t)MROWS * KDIM];
__device__ __align__(256) __nv_bfloat16 g_xl[(size_t)MROWS * KDIM];
__device__ __align__(256) __nv_bfloat16 g_wth[(size_t)NQKUV * KDIM]; // [N][K]
__device__ __align__(256) __nv_bfloat16 g_wtl[(size_t)NQKUV * KDIM];
__device__ __align__(256) __nv_bfloat16 g_fh[(size_t)MROWS * KDIM];
__device__ __align__(256) __nv_bfloat16 g_fl[(size_t)MROWS * KDIM];

__device__ __forceinline__ float silu_f(float x) { return x / (1.0f + expf(-x)); }

__device__ __forceinline__ uint32_t smem_u32(const void* p) {
    uint32_t a;
    asm("{ .reg .u64 t; cvta.to.shared.u64 t, %1; cvt.u32.u64 %0, t; }" : "=r"(a) : "l"(p));
    return a;
}

// ---------------------------------------------------------------------------
// Split helpers
// ---------------------------------------------------------------------------
__global__ void split_rows(const float* __restrict__ src,
                           __nv_bfloat16* __restrict__ h,
                           __nv_bfloat16* __restrict__ l)
{
    int i = blockIdx.x * blockDim.x + threadIdx.x;
    float4 v = ((const float4*)src)[i];
    float a[4] = {v.x, v.y, v.z, v.w};
    ushort4 ho, lo;
    unsigned short* hp = &ho.x; unsigned short* lp = &lo.x;
    #pragma unroll
    for (int j = 0; j < 4; j++) {
        __nv_bfloat16 hb = __float2bfloat16(a[j]);
        __nv_bfloat16 lb = __float2bfloat16(a[j] - __bfloat162float(hb));
        hp[j] = __bfloat16_as_ushort(hb);
        lp[j] = __bfloat16_as_ushort(lb);
    }
    ((ushort4*)h)[i] = ho;
    ((ushort4*)l)[i] = lo;
}

// W[K][N] -> WT_h/l[N][K] (bf16 split), 32x32 tiles
__global__ void splitT(const float* __restrict__ W,
                       __nv_bfloat16* __restrict__ h,
                       __nv_bfloat16* __restrict__ l, int N)
{
    __shared__ float t[32][33];
    int n0 = blockIdx.x * 32, k0 = blockIdx.y * 32;
    int tx = threadIdx.x, ty = threadIdx.y;          // block 32x8
    #pragma unroll
    for (int j = 0; j < 4; j++)
        t[ty + j*8][tx] = W[(size_t)(k0 + ty + j*8) * N + n0 + tx];
    __syncthreads();
    #pragma unroll
    for (int j = 0; j < 4; j++) {
        float v = t[tx][ty + j*8];
        __nv_bfloat16 hb = __float2bfloat16(v);
        __nv_bfloat16 lb = __float2bfloat16(v - __bfloat162float(hb));
        size_t idx = (size_t)(n0 + ty + j*8) * KDIM + k0 + tx;
        h[idx] = hb; l[idx] = lb;
    }
}

// ---------------------------------------------------------------------------
// mma.sync bf16 split GEMM: C[M,N] = (silu?)(A @ W^T), A=[M,K] hi/lo bf16,
// WT=[N,K] hi/lo bf16. CTA tile 128x128, warp tile 32x64, K-chunk 32,
// double-buffered cp.async. 3-term fp32 emulation: AhBh + AhBl + AlBh.
// ---------------------------------------------------------------------------
#define LDT 40                      // padded row length (bf16) -> 80B, conflict-free
#define TSTG (128 * LDT)            // elems per tile
#define STAGE_E (4 * TSTG)          // 4 tiles (Ah,Al,Bh,Bl) per stage
#define SMEM_MMA (2 * STAGE_E * 2)  // bytes = 81920

__device__ __forceinline__ void mma_bf16(float* d, const uint32_t* a, const uint32_t* b) {
    asm volatile(
        "mma.sync.aligned.m16n8k16.row.col.f32.bf16.bf16.f32 "
        "{%0,%1,%2,%3}, {%4,%5,%6,%7}, {%8,%9}, {%0,%1,%2,%3};"
        : "+f"(d[0]), "+f"(d[1]), "+f"(d[2]), "+f"(d[3])
        : "r"(a[0]), "r"(a[1]), "r"(a[2]), "r"(a[3]), "r"(b[0]), "r"(b[1]));
}

__device__ __forceinline__ void ldm_x4(uint32_t* r, uint32_t addr) {
    asm volatile("ldmatrix.sync.aligned.m8n8.x4.shared.b16 {%0,%1,%2,%3}, [%4];"
                 : "=r"(r[0]), "=r"(r[1]), "=r"(r[2]), "=r"(r[3]) : "r"(addr));
}

__device__ __forceinline__ void cp16(uint32_t dst, const void* src) {
    asm volatile("cp.async.cg.shared.global [%0], [%1], 16;" :: "r"(dst), "l"(src));
}

template<bool SILU>
__global__ __launch_bounds__(256, 2) void gemm_mma(
    const __nv_bfloat16* __restrict__ Ah, const __nv_bfloat16* __restrict__ Al,
    const __nv_bfloat16* __restrict__ Bh, const __nv_bfloat16* __restrict__ Bl,
    float* __restrict__ C, int Ndim)
{
    extern __shared__ __align__(128) char sm[];
    const uint32_t smb = smem_u32(sm);
    const int tid = threadIdx.x;
    const int lane = tid & 31, wid = tid >> 5;
    const int wm = wid >> 1, wn = wid & 1;          // 4x2 warps
    const int m0 = blockIdx.y * 128, n0 = blockIdx.x * 128;

    const __nv_bfloat16* gsrc[4] = {
        Ah + (size_t)m0 * KDIM, Al + (size_t)m0 * KDIM,
        Bh + (size_t)n0 * KDIM, Bl + (size_t)n0 * KDIM };

    // per-thread load slots: 4 matrices x 2 chunks (512 16B-chunks per matrix)
    auto load_stage = [&](int s, int k0) {
        #pragma unroll
        for (int mmat = 0; mmat < 4; mmat++) {
            uint32_t tbase = smb + (uint32_t)(s * STAGE_E + mmat * TSTG) * 2;
            #pragma unroll
            for (int i = 0; i < 2; i++) {
                int chunk = tid + i * 256;
                int row = chunk >> 2, seg = chunk & 3;
                cp16(tbase + (uint32_t)(row * LDT + seg * 8) * 2,
                     gsrc[mmat] + (size_t)row * KDIM + k0 + seg * 8);
            }
        }
        asm volatile("cp.async.commit_group;" ::: "memory");
    };

    float acc[2][8][4];
    #pragma unroll
    for (int i = 0; i < 2; i++)
        #pragma unroll
        for (int j = 0; j < 8; j++)
            #pragma unroll
            for (int q = 0; q < 4; q++) acc[i][j][q] = 0.0f;

    const int NS = KDIM / 32;
    load_stage(0, 0);

    const int arow = wm * 32 + (lane & 15);
    const int acol = (lane >> 4) * 8;
    const int brow = wn * 64 + (lane & 7) + (lane >> 4) * 8;
    const int bcol = ((lane >> 3) & 1) * 8;

    for (int st = 0; st < NS; st++) {
        if (st + 1 < NS) {
            load_stage((st + 1) & 1, (st + 1) * 32);
            asm volatile("cp.async.wait_group 1;" ::: "memory");
        } else {
            asm volatile("cp.async.wait_group 0;" ::: "memory");
        }
        __syncthreads();

        uint32_t sb = smb + (uint32_t)((st & 1) * STAGE_E) * 2;
        uint32_t ah_b = sb;
        uint32_t al_b = sb + (uint32_t)TSTG * 2;
        uint32_t bh_b = sb + (uint32_t)(2 * TSTG) * 2;
        uint32_t bl_b = sb + (uint32_t)(3 * TSTG) * 2;

        #pragma unroll
        for (int ks = 0; ks < 32; ks += 16) {
            uint32_t ra_h[2][4], ra_l[2][4];
            #pragma unroll
            for (int mt = 0; mt < 2; mt++) {
                uint32_t off = (uint32_t)((arow + mt * 16) * LDT + ks + acol) * 2;
                ldm_x4(ra_h[mt], ah_b + off);
                ldm_x4(ra_l[mt], al_b + off);
            }
            #pragma unroll
            for (int bhalf = 0; bhalf < 2; bhalf++) {
                uint32_t rb_h[2][4], rb_l[2][4];   // 2 x4 = 4 n-tiles each matrix
                #pragma unroll
                for (int bt = 0; bt < 2; bt++) {
                    uint32_t off = (uint32_t)((brow + bhalf * 32 + bt * 16) * LDT
                                              + ks + bcol) * 2;
                    ldm_x4(rb_h[bt], bh_b + off);
                    ldm_x4(rb_l[bt], bl_b + off);
                }
                #pragma unroll
                for (int mt = 0; mt < 2; mt++)
                    #pragma unroll
                    for (int nt = 0; nt < 4; nt++) {
                        float* d = acc[mt][bhalf * 4 + nt];
                        const uint32_t* bhf = &rb_h[nt >> 1][(nt & 1) * 2];
                        const uint32_t* blf = &rb_l[nt >> 1][(nt & 1) * 2];
                        mma_bf16(d, ra_h[mt], bhf);
                        mma_bf16(d, ra_h[mt], blf);
                        mma_bf16(d, ra_l[mt], bhf);
                    }
            }
        }
        __syncthreads();
    }

    // epilogue
    const int mbase = m0 + wm * 32 + (lane >> 2);
    const int nbase = n0 + wn * 64 + (lane & 3) * 2;
    #pragma unroll
    for (int mt = 0; mt < 2; mt++) {
        #pragma unroll
        for (int nt = 0; nt < 8; nt++) {
            float v0 = acc[mt][nt][0], v1 = acc[mt][nt][1];
            float v2 = acc[mt][nt][2], v3 = acc[mt][nt][3];
            if (SILU) { v0 = silu_f(v0); v1 = silu_f(v1); v2 = silu_f(v2); v3 = silu_f(v3); }
            int r = mbase + mt * 16, c = nbase + nt * 8;
            float2* p0 = (float2*)(C + (size_t)r * Ndim + c);
            float2* p1 = (float2*)(C + (size_t)(r + 8) * Ndim + c);
            *p0 = make_float2(v0, v1);
            *p1 = make_float2(v2, v3);
        }
    }
}

// ---------------------------------------------------------------------------
// RoPE in-place on q and k slices of g_qkuv
// ---------------------------------------------------------------------------
__global__ void rope_kernel(float* __restrict__ qkuv)
{
    int tid = blockIdx.x * blockDim.x + threadIdx.x;
    int i = tid & 31;
    int h = (tid >> 5) & (Hh - 1);
    int l = (tid >> 9) & (Ll - 1);
    int b = tid >> 20;
    float inv_freq = expf(-(float)i * 0.28782313662425583f);
    float theta = (float)l * inv_freq;
    float c = cosf(theta), s = sinf(theta);
    float* base = qkuv + ((size_t)(b * Ll + l)) * NQKUV + h * HD;
    float q0 = base[i], q1 = base[i + 32];
    base[i]      = q0 * c - q1 * s;
    base[i + 32] = q1 * c + q0 * s;
    float* kb = base + Dd;
    float k0 = kb[i], k1 = kb[i + 32];
    kb[i]      = k0 * c - k1 * s;
    kb[i + 32] = k1 * c + k0 * s;
}

// ---------------------------------------------------------------------------
// Fused attention (fp32 CUDA-core)
// ---------------------------------------------------------------------------
#define PADQ 132
#define PADS 129
__global__ __launch_bounds__(256) void attn_kernel(
    const float* __restrict__ qkuv, const float* __restrict__ attn_mask,
    const float* __restrict__ cmask, const float* __restrict__ cbias,
    float* __restrict__ out)
{
    extern __shared__ __align__(1024) char smraw[];
    float* smf = (float*)smraw;
    float* qsT = smf;
    float* ksT = qsT + 64 * PADQ;
    float* vs  = ksT + 64 * PADQ;
    float* ssT = vs + 128 * 64;

    const int tid = threadIdx.x;
    const int tr = tid >> 4, tc = tid & 15;
    const int b = blockIdx.z, h = blockIdx.y;
    const int l0 = blockIdx.x * 128;
    const float cb = cbias[h];

    const float* qbase = qkuv + (size_t)(b * Ll) * NQKUV + h * HD;
    const float* kbase = qbase + Dd;
    const float* vbase = qbase + 2 * Dd;

    #pragma unroll
    for (int i = 0; i < 8; i++) {
        int f = tid + i * 256;
        int l = f >> 4, c4 = f & 15;
        float4 v = *(const float4*)(qbase + (size_t)(l0 + l) * NQKUV + c4 * 4);
        qsT[(c4*4+0)*PADQ + l] = v.x;
        qsT[(c4*4+1)*PADQ + l] = v.y;
        qsT[(c4*4+2)*PADQ + l] = v.z;
        qsT[(c4*4+3)*PADQ + l] = v.w;
    }

    float accd[8][4] = {};

    for (int mt = 0; mt < Ll / 128; mt++) {
        const int m0 = mt * 128;
        #pragma unroll
        for (int i = 0; i < 8; i++) {
            int f = tid + i * 256;
            int m = f >> 4, c4 = f & 15;
            float4 kv = *(const float4*)(kbase + (size_t)(m0 + m) * NQKUV + c4 * 4);
            ksT[(c4*4+0)*PADQ + m] = kv.x;
            ksT[(c4*4+1)*PADQ + m] = kv.y;
            ksT[(c4*4+2)*PADQ + m] = kv.z;
            ksT[(c4*4+3)*PADQ + m] = kv.w;
            *(float4*)&vs[m * 64 + c4 * 4] =
                *(const float4*)(vbase + (size_t)(m0 + m) * NQKUV + c4 * 4);
        }
        __syncthreads();

        float sacc[8][8] = {};
        #pragma unroll 4
        for (int k = 0; k < 64; k++) {
            float ra[8], rb[8];
            *(float4*)&ra[0] = *(float4*)&qsT[k*PADQ + tr*8];
            *(float4*)&ra[4] = *(float4*)&qsT[k*PADQ + tr*8 + 4];
            *(float4*)&rb[0] = *(float4*)&ksT[k*PADQ + tc*8];
            *(float4*)&rb[4] = *(float4*)&ksT[k*PADQ + tc*8 + 4];
            #pragma unroll
            for (int i = 0; i < 8; i++)
                #pragma unroll
                for (int j = 0; j < 8; j++)
                    sacc[i][j] += ra[i] * rb[j];
        }

        float cmv[8];
        *(float4*)&cmv[0] = *(const float4*)(cmask + b * Ll + m0 + tc*8);
        *(float4*)&cmv[4] = *(const float4*)(cmask + b * Ll + m0 + tc*8 + 4);
        #pragma unroll
        for (int i = 0; i < 8; i++) {
            int lg = l0 + tr*8 + i;
            const float* mrow = attn_mask + ((size_t)b * Ll + lg) * Ll + m0 + tc*8;
            float4 mk0 = *(const float4*)mrow;
            float4 mk1 = *(const float4*)(mrow + 4);
            float mk[8] = {mk0.x, mk0.y, mk0.z, mk0.w, mk1.x, mk1.y, mk1.z, mk1.w};
            #pragma unroll
            for (int j = 0; j < 8; j++) {
                float xv = sacc[i][j] * 0.125f + cmv[j] * cb;
                sacc[i][j] = (xv / (1.0f + expf(-xv))) * mk[j];
            }
        }

        #pragma unroll
        for (int j = 0; j < 8; j++)
            #pragma unroll
            for (int i = 0; i < 8; i++)
                ssT[(tc*8 + j) * PADS + tr*8 + i] = sacc[i][j];
        __syncthreads();

        #pragma unroll 4
        for (int k = 0; k < 128; k++) {
            float ra[8];
            float4 rb = *(float4*)&vs[k * 64 + tc * 4];
            #pragma unroll
            for (int i = 0; i < 8; i++) ra[i] = ssT[k * PADS + tr*8 + i];
            #pragma unroll
            for (int i = 0; i < 8; i++) {
                accd[i][0] += ra[i] * rb.x;
                accd[i][1] += ra[i] * rb.y;
                accd[i][2] += ra[i] * rb.z;
                accd[i][3] += ra[i] * rb.w;
            }
        }
        __syncthreads();
    }

    float* obase = out + ((size_t)(b * Hh + h) * Ll + l0) * HD;
    #pragma unroll
    for (int i = 0; i < 8; i++)
        *(float4*)&obase[(tr*8 + i) * HD + tc * 4] = *(float4*)&accd[i][0];
}

// ---------------------------------------------------------------------------
// LayerNorm(d) + u-gate; writes split-bf16 (B,L,D) directly for the out GEMM
// ---------------------------------------------------------------------------
__global__ void ln_gate_kernel(
    const float* __restrict__ attn, const float* __restrict__ qkuv,
    const float* __restrict__ gamma, const float* __restrict__ beta,
    __nv_bfloat16* __restrict__ fh, __nv_bfloat16* __restrict__ fl)
{
    int warp = (blockIdx.x * blockDim.x + threadIdx.x) >> 5;
    int lane = threadIdx.x & 31;
    int l = warp & (Ll - 1);
    int h = (warp >> 11) & (Hh - 1);
    int b = warp >> 15;
    const float* row = attn + (size_t)warp * HD;
    float v0 = row[lane], v1 = row[lane + 32];
    float s = v0 + v1, sq = v0 * v0 + v1 * v1;
    #pragma unroll
    for (int o = 16; o > 0; o >>= 1) {
        s  += __shfl_xor_sync(0xFFFFFFFFu, s,  o);
        sq += __shfl_xor_sync(0xFFFFFFFFu, sq, o);
    }
    float mu = s * (1.0f / 64.0f);
    float var = sq * (1.0f / 64.0f) - mu * mu;
    float rstd = rsqrtf(var + 1e-5f);
    const float* ub = qkuv + ((size_t)(b * Ll + l)) * NQKUV + 3 * Dd + h * HD;
    size_t ob = ((size_t)(b * Ll + l)) * Dd + h * HD;
    float y0 = ((v0 - mu) * rstd * gamma[lane]      + beta[lane])      * ub[lane];
    float y1 = ((v1 - mu) * rstd * gamma[lane + 32] + beta[lane + 32]) * ub[lane + 32];
    __nv_bfloat16 h0 = __float2bfloat16(y0);
    __nv_bfloat16 h1 = __float2bfloat16(y1);
    fh[ob + lane]      = h0;
    fh[ob + lane + 32] = h1;
    fl[ob + lane]      = __float2bfloat16(y0 - __bfloat162float(h0));
    fl[ob + lane + 32] = __float2bfloat16(y1 - __bfloat162float(h1));
}

// ---------------------------------------------------------------------------
extern "C" void kernel_launch(void* const* d_in, const int* in_sizes, int n_in,
                              void* d_out, int out_size)
{
    const float *x = nullptr, *attn_mask = nullptr, *cmask = nullptr;
    const float *Wqkuv = nullptr, *Wout = nullptr;
    const float *gamma = nullptr, *beta = nullptr, *cbias = nullptr;
    for (int i = 0; i < n_in; i++) {
        const float* p = (const float*)d_in[i];
        switch (in_sizes[i]) {
            case MROWS * Dd:        x = p; break;
            case Bb * Ll * Ll:      attn_mask = p; break;
            case Bb * Ll:           cmask = p; break;
            case Dd * NQKUV:        Wqkuv = p; break;
            case Dd * Dd:           Wout = p; break;
            case HD:                if (!gamma) gamma = p; else beta = p; break;
            case Hh:                cbias = p; break;
            default: break;
        }
    }
    float* out = (float*)d_out;

    float *qkuv, *attn;
    __nv_bfloat16 *xh, *xl, *wth, *wtl, *fh, *fl;
    cudaGetSymbolAddress((void**)&qkuv, g_qkuv);
    cudaGetSymbolAddress((void**)&attn, g_attn);
    cudaGetSymbolAddress((void**)&xh,  g_xh);
    cudaGetSymbolAddress((void**)&xl,  g_xl);
    cudaGetSymbolAddress((void**)&wth, g_wth);
    cudaGetSymbolAddress((void**)&wtl, g_wtl);
    cudaGetSymbolAddress((void**)&fh,  g_fh);
    cudaGetSymbolAddress((void**)&fl,  g_fl);

    const int ATTN_SMEM = (64 * PADQ * 2 + 128 * 64 + 128 * PADS) * (int)sizeof(float);
    cudaFuncSetAttribute(attn_kernel, cudaFuncAttributeMaxDynamicSharedMemorySize, ATTN_SMEM);
    cudaFuncSetAttribute(gemm_mma<true>,  cudaFuncAttributeMaxDynamicSharedMemorySize, SMEM_MMA);
    cudaFuncSetAttribute(gemm_mma<false>, cudaFuncAttributeMaxDynamicSharedMemorySize, SMEM_MMA);

    // 1) split inputs to bf16 hi/lo
    split_rows<<<(MROWS * KDIM / 4) / 256, 256>>>(x, xh, xl);
    splitT<<<dim3(NQKUV / 32, KDIM / 32), dim3(32, 8)>>>(Wqkuv, wth, wtl, NQKUV);

    // 2) qkuv = silu(x @ Wqkuv) via mma.sync bf16 split-3
    gemm_mma<true><<<dim3(NQKUV / 128, MROWS / 128), 256, SMEM_MMA>>>(
        xh, xl, wth, wtl, qkuv, NQKUV);

    // 3) RoPE on q, k (in place)
    rope_kernel<<<(Bb * Ll * Hh * 32) / 256, 256>>>(qkuv);

    // 4) fused scores + SiLU + mask + S@V
    attn_kernel<<<dim3(Ll / 128, Hh, Bb), 256, ATTN_SMEM>>>(
        qkuv, attn_mask, cmask, cbias, attn);

    // 5) LayerNorm(d) + u-gate -> split bf16 (B,L,D)
    ln_gate_kernel<<<(Bb * Hh * Ll * 32) / 256, 256>>>(attn, qkuv, gamma, beta, fh, fl);

    // 6) out = flat @ Wout via mma.sync
    splitT<<<dim3(Dd / 32, KDIM / 32), dim3(32, 8)>>>(Wout, wth, wtl, Dd);
    gemm_mma<false><<<dim3(Dd / 128, MROWS / 128), 256, SMEM_MMA>>>(
        fh, fl, wth, wtl, out, Dd);
}

// round 4
// speedup vs baseline: 2.5091x; 1.8233x over previous
#include <cuda_runtime.h>
#include <cuda_bf16.h>
#include <math.h>
#include <stdint.h>

#define Bb 4
#define Ll 2048
#define Dd 1024
#define Hh 16
#define HD 64
#define MROWS (Bb*Ll)        // 8192
#define NQKUV (4*Dd)         // 4096
#define KDIM  Dd             // 1024

// ---------------- scratch (device globals; no cudaMalloc allowed) ----------
__device__ float g_qkuv[(size_t)MROWS * NQKUV];                 // 128 MB
__device__ float g_attn[(size_t)Bb*Hh*Ll*HD];                   // 32 MB
__device__ __align__(256) __nv_bfloat16 g_xh[(size_t)MROWS * KDIM];
__device__ __align__(256) __nv_bfloat16 g_xl[(size_t)MROWS * KDIM];
__device__ __align__(256) __nv_bfloat16 g_wth[(size_t)NQKUV * KDIM]; // [N][K]
__device__ __align__(256) __nv_bfloat16 g_wtl[(size_t)NQKUV * KDIM];
__device__ __align__(256) __nv_bfloat16 g_fh[(size_t)MROWS * KDIM];
__device__ __align__(256) __nv_bfloat16 g_fl[(size_t)MROWS * KDIM];
// attention operands, head-major
__device__ __align__(256) __nv_bfloat16 g_qh[(size_t)Bb*Hh*Ll*HD];
__device__ __align__(256) __nv_bfloat16 g_ql[(size_t)Bb*Hh*Ll*HD];
__device__ __align__(256) __nv_bfloat16 g_kh[(size_t)Bb*Hh*Ll*HD];
__device__ __align__(256) __nv_bfloat16 g_kl[(size_t)Bb*Hh*Ll*HD];
__device__ __align__(256) __nv_bfloat16 g_vth[(size_t)Bb*Hh*HD*Ll];  // [b,h,d,L]
__device__ __align__(256) __nv_bfloat16 g_vtl[(size_t)Bb*Hh*HD*Ll];

__device__ __forceinline__ float silu_f(float x) { return x / (1.0f + expf(-x)); }

__device__ __forceinline__ uint32_t smem_u32(const void* p) {
    uint32_t a;
    asm("{ .reg .u64 t; cvta.to.shared.u64 t, %1; cvt.u32.u64 %0, t; }" : "=r"(a) : "l"(p));
    return a;
}

__device__ __forceinline__ void split_store(__nv_bfloat16* h, __nv_bfloat16* l,
                                            size_t idx, float v) {
    __nv_bfloat16 hb = __float2bfloat16(v);
    h[idx] = hb;
    l[idx] = __float2bfloat16(v - __bfloat162float(hb));
}

__device__ __forceinline__ uint32_t pack_bf2(float a, float b) {
    __nv_bfloat162 t = __floats2bfloat162_rn(a, b);
    return *(uint32_t*)&t;
}

// ---------------------------------------------------------------------------
// Split helpers for projections
// ---------------------------------------------------------------------------
__global__ void split_rows(const float* __restrict__ src,
                           __nv_bfloat16* __restrict__ h,
                           __nv_bfloat16* __restrict__ l)
{
    int i = blockIdx.x * blockDim.x + threadIdx.x;
    float4 v = ((const float4*)src)[i];
    float a[4] = {v.x, v.y, v.z, v.w};
    ushort4 ho, lo;
    unsigned short* hp = &ho.x; unsigned short* lp = &lo.x;
    #pragma unroll
    for (int j = 0; j < 4; j++) {
        __nv_bfloat16 hb = __float2bfloat16(a[j]);
        __nv_bfloat16 lb = __float2bfloat16(a[j] - __bfloat162float(hb));
        hp[j] = __bfloat16_as_ushort(hb);
        lp[j] = __bfloat16_as_ushort(lb);
    }
    ((ushort4*)h)[i] = ho;
    ((ushort4*)l)[i] = lo;
}

__global__ void splitT(const float* __restrict__ W,
                       __nv_bfloat16* __restrict__ h,
                       __nv_bfloat16* __restrict__ l, int N)
{
    __shared__ float t[32][33];
    int n0 = blockIdx.x * 32, k0 = blockIdx.y * 32;
    int tx = threadIdx.x, ty = threadIdx.y;
    #pragma unroll
    for (int j = 0; j < 4; j++)
        t[ty + j*8][tx] = W[(size_t)(k0 + ty + j*8) * N + n0 + tx];
    __syncthreads();
    #pragma unroll
    for (int j = 0; j < 4; j++) {
        float v = t[tx][ty + j*8];
        size_t idx = (size_t)(n0 + ty + j*8) * KDIM + k0 + tx;
        split_store(h, l, idx, v);
    }
}

// ---------------------------------------------------------------------------
// mma.sync primitives
// ---------------------------------------------------------------------------
__device__ __forceinline__ void mma_bf16(float* d, const uint32_t* a, const uint32_t* b) {
    asm volatile(
        "mma.sync.aligned.m16n8k16.row.col.f32.bf16.bf16.f32 "
        "{%0,%1,%2,%3}, {%4,%5,%6,%7}, {%8,%9}, {%0,%1,%2,%3};"
        : "+f"(d[0]), "+f"(d[1]), "+f"(d[2]), "+f"(d[3])
        : "r"(a[0]), "r"(a[1]), "r"(a[2]), "r"(a[3]), "r"(b[0]), "r"(b[1]));
}

__device__ __forceinline__ void ldm_x4(uint32_t* r, uint32_t addr) {
    asm volatile("ldmatrix.sync.aligned.m8n8.x4.shared.b16 {%0,%1,%2,%3}, [%4];"
                 : "=r"(r[0]), "=r"(r[1]), "=r"(r[2]), "=r"(r[3]) : "r"(addr));
}

__device__ __forceinline__ void cp16(uint32_t dst, const void* src) {
    asm volatile("cp.async.cg.shared.global [%0], [%1], 16;" :: "r"(dst), "l"(src));
}
__device__ __forceinline__ void cp_commit() {
    asm volatile("cp.async.commit_group;" ::: "memory");
}
__device__ __forceinline__ void cp_wait_all() {
    asm volatile("cp.async.wait_group 0;" ::: "memory");
}

// ---------------------------------------------------------------------------
// Projection GEMM (unchanged from round 3)
// ---------------------------------------------------------------------------
#define LDT 40
#define TSTG (128 * LDT)
#define STAGE_E (4 * TSTG)
#define SMEM_MMA (2 * STAGE_E * 2)

template<bool SILU>
__global__ __launch_bounds__(256, 2) void gemm_mma(
    const __nv_bfloat16* __restrict__ Ah, const __nv_bfloat16* __restrict__ Al,
    const __nv_bfloat16* __restrict__ Bh, const __nv_bfloat16* __restrict__ Bl,
    float* __restrict__ C, int Ndim)
{
    extern __shared__ __align__(128) char sm[];
    const uint32_t smb = smem_u32(sm);
    const int tid = threadIdx.x;
    const int lane = tid & 31, wid = tid >> 5;
    const int wm = wid >> 1, wn = wid & 1;
    const int m0 = blockIdx.y * 128, n0 = blockIdx.x * 128;

    const __nv_bfloat16* gsrc[4] = {
        Ah + (size_t)m0 * KDIM, Al + (size_t)m0 * KDIM,
        Bh + (size_t)n0 * KDIM, Bl + (size_t)n0 * KDIM };

    auto load_stage = [&](int s, int k0) {
        #pragma unroll
        for (int mmat = 0; mmat < 4; mmat++) {
            uint32_t tbase = smb + (uint32_t)(s * STAGE_E + mmat * TSTG) * 2;
            #pragma unroll
            for (int i = 0; i < 2; i++) {
                int chunk = tid + i * 256;
                int row = chunk >> 2, seg = chunk & 3;
                cp16(tbase + (uint32_t)(row * LDT + seg * 8) * 2,
                     gsrc[mmat] + (size_t)row * KDIM + k0 + seg * 8);
            }
        }
        cp_commit();
    };

    float acc[2][8][4];
    #pragma unroll
    for (int i = 0; i < 2; i++)
        #pragma unroll
        for (int j = 0; j < 8; j++)
            #pragma unroll
            for (int q = 0; q < 4; q++) acc[i][j][q] = 0.0f;

    const int NS = KDIM / 32;
    load_stage(0, 0);

    const int arow = wm * 32 + (lane & 15);
    const int acol = (lane >> 4) * 8;
    const int brow = wn * 64 + (lane & 7) + (lane >> 4) * 8;
    const int bcol = ((lane >> 3) & 1) * 8;

    for (int st = 0; st < NS; st++) {
        if (st + 1 < NS) {
            load_stage((st + 1) & 1, (st + 1) * 32);
            asm volatile("cp.async.wait_group 1;" ::: "memory");
        } else {
            cp_wait_all();
        }
        __syncthreads();

        uint32_t sb = smb + (uint32_t)((st & 1) * STAGE_E) * 2;
        uint32_t ah_b = sb;
        uint32_t al_b = sb + (uint32_t)TSTG * 2;
        uint32_t bh_b = sb + (uint32_t)(2 * TSTG) * 2;
        uint32_t bl_b = sb + (uint32_t)(3 * TSTG) * 2;

        #pragma unroll
        for (int ks = 0; ks < 32; ks += 16) {
            uint32_t ra_h[2][4], ra_l[2][4];
            #pragma unroll
            for (int mt = 0; mt < 2; mt++) {
                uint32_t off = (uint32_t)((arow + mt * 16) * LDT + ks + acol) * 2;
                ldm_x4(ra_h[mt], ah_b + off);
                ldm_x4(ra_l[mt], al_b + off);
            }
            #pragma unroll
            for (int bhalf = 0; bhalf < 2; bhalf++) {
                uint32_t rb_h[2][4], rb_l[2][4];
                #pragma unroll
                for (int bt = 0; bt < 2; bt++) {
                    uint32_t off = (uint32_t)((brow + bhalf * 32 + bt * 16) * LDT
                                              + ks + bcol) * 2;
                    ldm_x4(rb_h[bt], bh_b + off);
                    ldm_x4(rb_l[bt], bl_b + off);
                }
                #pragma unroll
                for (int mt = 0; mt < 2; mt++)
                    #pragma unroll
                    for (int nt = 0; nt < 4; nt++) {
                        float* d = acc[mt][bhalf * 4 + nt];
                        const uint32_t* bhf = &rb_h[nt >> 1][(nt & 1) * 2];
                        const uint32_t* blf = &rb_l[nt >> 1][(nt & 1) * 2];
                        mma_bf16(d, ra_h[mt], bhf);
                        mma_bf16(d, ra_h[mt], blf);
                        mma_bf16(d, ra_l[mt], bhf);
                    }
            }
        }
        __syncthreads();
    }

    const int mbase = m0 + wm * 32 + (lane >> 2);
    const int nbase = n0 + wn * 64 + (lane & 3) * 2;
    #pragma unroll
    for (int mt = 0; mt < 2; mt++) {
        #pragma unroll
        for (int nt = 0; nt < 8; nt++) {
            float v0 = acc[mt][nt][0], v1 = acc[mt][nt][1];
            float v2 = acc[mt][nt][2], v3 = acc[mt][nt][3];
            if (SILU) { v0 = silu_f(v0); v1 = silu_f(v1); v2 = silu_f(v2); v3 = silu_f(v3); }
            int r = mbase + mt * 16, c = nbase + nt * 8;
            *(float2*)(C + (size_t)r * Ndim + c) = make_float2(v0, v1);
            *(float2*)(C + (size_t)(r + 8) * Ndim + c) = make_float2(v2, v3);
        }
    }
}

// ---------------------------------------------------------------------------
// Prep 1: RoPE + hi/lo split q,k -> head-major [b,h,l,64]
// ---------------------------------------------------------------------------
__global__ void rope_split_qk(const float* __restrict__ qkuv,
    __nv_bfloat16* __restrict__ qh, __nv_bfloat16* __restrict__ ql,
    __nv_bfloat16* __restrict__ kh, __nv_bfloat16* __restrict__ kl)
{
    int tid = blockIdx.x * blockDim.x + threadIdx.x;
    int i = tid & 31;
    int h = (tid >> 5) & (Hh - 1);
    int l = (tid >> 9) & (Ll - 1);
    int b = tid >> 20;
    float inv_freq = expf(-(float)i * 0.28782313662425583f);
    float theta = (float)l * inv_freq;
    float c = cosf(theta), s = sinf(theta);
    const float* base = qkuv + ((size_t)(b * Ll + l)) * NQKUV + h * HD;
    float q0 = base[i], q1 = base[i + 32];
    float k0 = base[Dd + i], k1 = base[Dd + i + 32];
    float qr0 = q0 * c - q1 * s, qr1 = q1 * c + q0 * s;
    float kr0 = k0 * c - k1 * s, kr1 = k1 * c + k0 * s;
    size_t o = ((size_t)((b * Hh + h) * Ll) + l) * HD;
    split_store(qh, ql, o + i,      qr0);
    split_store(qh, ql, o + i + 32, qr1);
    split_store(kh, kl, o + i,      kr0);
    split_store(kh, kl, o + i + 32, kr1);
}

// ---------------------------------------------------------------------------
// Prep 2: V transpose + split -> [b,h,d,L]
// ---------------------------------------------------------------------------
__global__ void vtrans_split(const float* __restrict__ qkuv,
    __nv_bfloat16* __restrict__ vth, __nv_bfloat16* __restrict__ vtl)
{
    __shared__ float ts[64][65];
    int b = blockIdx.z, h = blockIdx.y, l0 = blockIdx.x * 64;
    int tid = threadIdx.x;
    const float* vsrc = qkuv + (size_t)(b * Ll + l0) * NQKUV + 2 * Dd + h * HD;
    #pragma unroll
    for (int k = 0; k < 4; k++) {
        int c = tid + k * 256;              // 1024 float4
        int r = c >> 4, c4 = c & 15;
        float4 v = *(const float4*)(vsrc + (size_t)r * NQKUV + c4 * 4);
        ts[r][c4*4+0] = v.x; ts[r][c4*4+1] = v.y;
        ts[r][c4*4+2] = v.z; ts[r][c4*4+3] = v.w;
    }
    __syncthreads();
    size_t obase = ((size_t)((b * Hh + h) * HD)) * Ll + l0;
    #pragma unroll
    for (int k = 0; k < 4; k++) {
        int c = tid + k * 256;
        int d = c >> 4, j4 = c & 15;
        ushort4 ho, lo;
        unsigned short* hp = &ho.x; unsigned short* lp = &lo.x;
        #pragma unroll
        for (int j = 0; j < 4; j++) {
            float v = ts[j4*4 + j][d];
            __nv_bfloat16 hb = __float2bfloat16(v);
            hp[j] = __bfloat16_as_ushort(hb);
            lp[j] = __bfloat16_as_ushort(__float2bfloat16(v - __bfloat162float(hb)));
        }
        *(ushort4*)(vth + obase + (size_t)d * Ll + j4 * 4) = ho;
        *(ushort4*)(vtl + obase + (size_t)d * Ll + j4 * 4) = lo;
    }
}

// ---------------------------------------------------------------------------
// HMMA attention. CTA = (l-tile 128, h, b). 256 threads, 8 warps (4x2).
// QK: 3-term hi/lo bf16; SiLU epilogue; S re-split hi/lo; SV: 3-term.
// ---------------------------------------------------------------------------
#define ALD 72      // q/k smem pitch (bf16)
#define SLD 136     // S/vT smem pitch (bf16)
#define A_QH 0
#define A_QL 18432
#define A_KH 36864
#define A_KL 55296
#define A_VH 73728
#define A_VL 91136
#define A_SH 108544
#define A_SL 143360
#define A_TOT 178176

__global__ __launch_bounds__(256) void attn_mma(
    const __nv_bfloat16* __restrict__ qh_g, const __nv_bfloat16* __restrict__ ql_g,
    const __nv_bfloat16* __restrict__ kh_g, const __nv_bfloat16* __restrict__ kl_g,
    const __nv_bfloat16* __restrict__ vth_g, const __nv_bfloat16* __restrict__ vtl_g,
    const float* __restrict__ attn_mask, const float* __restrict__ cmask,
    const float* __restrict__ cbias, float* __restrict__ out)
{
    extern __shared__ __align__(128) char sm[];
    const uint32_t smb = smem_u32(sm);
    const int tid = threadIdx.x;
    const int lane = tid & 31, wid = tid >> 5;
    const int wm = wid >> 1, wn = wid & 1;
    const int b = blockIdx.z, h = blockIdx.y;
    const int l0 = blockIdx.x * 128;
    const size_t bh = (size_t)(b * Hh + h);
    const float cb = cbias[h];

    const __nv_bfloat16* qh_p = qh_g + (bh * Ll + l0) * HD;
    const __nv_bfloat16* ql_p = ql_g + (bh * Ll + l0) * HD;
    const __nv_bfloat16* kh_p = kh_g + bh * Ll * HD;
    const __nv_bfloat16* kl_p = kl_g + bh * Ll * HD;
    const __nv_bfloat16* vth_p = vth_g + bh * HD * Ll;
    const __nv_bfloat16* vtl_p = vtl_g + bh * HD * Ll;

    auto load_k = [&](int m0) {
        #pragma unroll
        for (int i = 0; i < 4; i++) {
            int c = tid + i * 256;
            int row = c >> 3, seg = c & 7;
            uint32_t d = (uint32_t)(row * 144 + seg * 16);
            const size_t gsrc = (size_t)(m0 + row) * HD + seg * 8;
            cp16(smb + A_KH + d, kh_p + gsrc);
            cp16(smb + A_KL + d, kl_p + gsrc);
        }
        cp_commit();
    };
    auto load_v = [&](int m0) {
        #pragma unroll
        for (int i = 0; i < 4; i++) {
            int c = tid + i * 256;
            int row = c >> 4, seg = c & 15;
            uint32_t d = (uint32_t)(row * 272 + seg * 16);
            const size_t gsrc = (size_t)row * Ll + m0 + seg * 8;
            cp16(smb + A_VH + d, vth_p + gsrc);
            cp16(smb + A_VL + d, vtl_p + gsrc);
        }
        cp_commit();
    };

    // q tile (once)
    #pragma unroll
    for (int i = 0; i < 4; i++) {
        int c = tid + i * 256;
        int row = c >> 3, seg = c & 7;
        uint32_t d = (uint32_t)(row * 144 + seg * 16);
        cp16(smb + A_QH + d, qh_p + (size_t)row * HD + seg * 8);
        cp16(smb + A_QL + d, ql_p + (size_t)row * HD + seg * 8);
    }
    cp_commit();
    load_k(0);
    load_v(0);

    const int arow = wm * 32 + (lane & 15);
    const int acol = (lane >> 4) * 8;
    const int brow = (lane & 7) + (lane >> 4) * 8;
    const int bcol = ((lane >> 3) & 1) * 8;

    float oacc[2][4][4];
    #pragma unroll
    for (int i = 0; i < 2; i++)
        #pragma unroll
        for (int j = 0; j < 4; j++)
            #pragma unroll
            for (int q = 0; q < 4; q++) oacc[i][j][q] = 0.0f;

    for (int mt8 = 0; mt8 < 16; mt8++) {
        const int m0 = mt8 * 128;
        cp_wait_all();
        __syncthreads();

        // ---- QK: S[l 128][m 128], 3-term ----
        float sacc[2][8][4];
        #pragma unroll
        for (int i = 0; i < 2; i++)
            #pragma unroll
            for (int j = 0; j < 8; j++)
                #pragma unroll
                for (int q = 0; q < 4; q++) sacc[i][j][q] = 0.0f;

        #pragma unroll
        for (int ks = 0; ks < 64; ks += 16) {
            uint32_t fah[2][4], fal[2][4];
            #pragma unroll
            for (int mt = 0; mt < 2; mt++) {
                uint32_t off = (uint32_t)((arow + mt * 16) * ALD + ks + acol) * 2;
                ldm_x4(fah[mt], smb + A_QH + off);
                ldm_x4(fal[mt], smb + A_QL + off);
            }
            #pragma unroll
            for (int half = 0; half < 2; half++) {
                uint32_t fbh[2][4], fbl[2][4];
                #pragma unroll
                for (int bt = 0; bt < 2; bt++) {
                    uint32_t off = (uint32_t)((wn * 64 + half * 32 + bt * 16 + brow) * ALD
                                              + ks + bcol) * 2;
                    ldm_x4(fbh[bt], smb + A_KH + off);
                    ldm_x4(fbl[bt], smb + A_KL + off);
                }
                #pragma unroll
                for (int mt = 0; mt < 2; mt++)
                    #pragma unroll
                    for (int nt = 0; nt < 4; nt++) {
                        float* d = sacc[mt][half * 4 + nt];
                        const uint32_t* bf = &fbh[nt >> 1][(nt & 1) * 2];
                        const uint32_t* bl = &fbl[nt >> 1][(nt & 1) * 2];
                        mma_bf16(d, fah[mt], bf);
                        mma_bf16(d, fah[mt], bl);
                        mma_bf16(d, fal[mt], bf);
                    }
            }
        }

        // ---- epilogue: scale + conv bias + SiLU + mask; S -> smem hi/lo ----
        float2 cm2[8];
        #pragma unroll
        for (int j = 0; j < 8; j++)
            cm2[j] = *(const float2*)(cmask + b * Ll + m0 + wn * 64 + j * 8 + (lane & 3) * 2);

        #pragma unroll
        for (int mt = 0; mt < 2; mt++) {
            int r = wm * 32 + mt * 16 + (lane >> 2);
            int rg = l0 + r;
            #pragma unroll
            for (int j = 0; j < 8; j++) {
                int cl = wn * 64 + j * 8 + (lane & 3) * 2;
                const float* mrow = attn_mask + ((size_t)b * Ll + rg) * Ll + m0 + cl;
                float2 mk0 = *(const float2*)mrow;
                float2 mk1 = *(const float2*)(mrow + (size_t)8 * Ll);
                float x0 = sacc[mt][j][0] * 0.125f + cm2[j].x * cb;
                float x1 = sacc[mt][j][1] * 0.125f + cm2[j].y * cb;
                float x2 = sacc[mt][j][2] * 0.125f + cm2[j].x * cb;
                float x3 = sacc[mt][j][3] * 0.125f + cm2[j].y * cb;
                float s0 = __fdividef(x0, 1.0f + expf(-x0)) * mk0.x;
                float s1 = __fdividef(x1, 1.0f + expf(-x1)) * mk0.y;
                float s2 = __fdividef(x2, 1.0f + expf(-x2)) * mk1.x;
                float s3 = __fdividef(x3, 1.0f + expf(-x3)) * mk1.y;
                // split hi/lo, pack pairs
                __nv_bfloat16 h0 = __float2bfloat16(s0), h1 = __float2bfloat16(s1);
                __nv_bfloat16 h2 = __float2bfloat16(s2), h3 = __float2bfloat16(s3);
                float l0f = s0 - __bfloat162float(h0), l1f = s1 - __bfloat162float(h1);
                float l2f = s2 - __bfloat162float(h2), l3f = s3 - __bfloat162float(h3);
                uint32_t o0 = (uint32_t)(r * SLD + cl) * 2;
                uint32_t o1 = (uint32_t)((r + 8) * SLD + cl) * 2;
                *(uint32_t*)(sm + A_SH + o0) =
                    (uint32_t)__bfloat16_as_ushort(h0) | ((uint32_t)__bfloat16_as_ushort(h1) << 16);
                *(uint32_t*)(sm + A_SH + o1) =
                    (uint32_t)__bfloat16_as_ushort(h2) | ((uint32_t)__bfloat16_as_ushort(h3) << 16);
                *(uint32_t*)(sm + A_SL + o0) = pack_bf2(l0f, l1f);
                *(uint32_t*)(sm + A_SL + o1) = pack_bf2(l2f, l3f);
            }
        }
        __syncthreads();          // S visible; all warps past QK (k region free)

        if (mt8 < 15) load_k(m0 + 128);   // prefetch next k (overlaps SV)

        // ---- SV: O[l 128][d 64] += S @ V, 3-term ----
        #pragma unroll
        for (int ks = 0; ks < 128; ks += 16) {
            uint32_t fsh[2][4], fsl[2][4];
            #pragma unroll
            for (int mt = 0; mt < 2; mt++) {
                uint32_t off = (uint32_t)((arow + mt * 16) * SLD + ks + acol) * 2;
                ldm_x4(fsh[mt], smb + A_SH + off);
                ldm_x4(fsl[mt], smb + A_SL + off);
            }
            uint32_t fvh[2][4], fvl[2][4];
            #pragma unroll
            for (int bt = 0; bt < 2; bt++) {
                uint32_t off = (uint32_t)((wn * 32 + bt * 16 + brow) * SLD + ks + bcol) * 2;
                ldm_x4(fvh[bt], smb + A_VH + off);
                ldm_x4(fvl[bt], smb + A_VL + off);
            }
            #pragma unroll
            for (int mt = 0; mt < 2; mt++)
                #pragma unroll
                for (int nt = 0; nt < 4; nt++) {
                    float* d = oacc[mt][nt];
                    const uint32_t* bf = &fvh[nt >> 1][(nt & 1) * 2];
                    const uint32_t* bl = &fvl[nt >> 1][(nt & 1) * 2];
                    mma_bf16(d, fsh[mt], bf);
                    mma_bf16(d, fsh[mt], bl);
                    mma_bf16(d, fsl[mt], bf);
                }
        }
        __syncthreads();          // vT reads done
        if (mt8 < 15) load_v(m0 + 128);
    }

    // ---- write O: [b,h,l,d] fp32 ----
    #pragma unroll
    for (int mt = 0; mt < 2; mt++) {
        int r = l0 + wm * 32 + mt * 16 + (lane >> 2);
        #pragma unroll
        for (int nt = 0; nt < 4; nt++) {
            int c = wn * 32 + nt * 8 + (lane & 3) * 2;
            *(float2*)(out + (bh * Ll + r) * HD + c) =
                make_float2(oacc[mt][nt][0], oacc[mt][nt][1]);
            *(float2*)(out + (bh * Ll + r + 8) * HD + c) =
                make_float2(oacc[mt][nt][2], oacc[mt][nt][3]);
        }
    }
}

// ---------------------------------------------------------------------------
// LayerNorm(d) + u-gate -> split bf16 (B,L,D)
// ---------------------------------------------------------------------------
__global__ void ln_gate_kernel(
    const float* __restrict__ attn, const float* __restrict__ qkuv,
    const float* __restrict__ gamma, const float* __restrict__ beta,
    __nv_bfloat16* __restrict__ fh, __nv_bfloat16* __restrict__ fl)
{
    int warp = (blockIdx.x * blockDim.x + threadIdx.x) >> 5;
    int lane = threadIdx.x & 31;
    int l = warp & (Ll - 1);
    int h = (warp >> 11) & (Hh - 1);
    int b = warp >> 15;
    const float* row = attn + (size_t)warp * HD;
    float v0 = row[lane], v1 = row[lane + 32];
    float s = v0 + v1, sq = v0 * v0 + v1 * v1;
    #pragma unroll
    for (int o = 16; o > 0; o >>= 1) {
        s  += __shfl_xor_sync(0xFFFFFFFFu, s,  o);
        sq += __shfl_xor_sync(0xFFFFFFFFu, sq, o);
    }
    float mu = s * (1.0f / 64.0f);
    float var = sq * (1.0f / 64.0f) - mu * mu;
    float rstd = rsqrtf(var + 1e-5f);
    const float* ub = qkuv + ((size_t)(b * Ll + l)) * NQKUV + 3 * Dd + h * HD;
    size_t ob = ((size_t)(b * Ll + l)) * Dd + h * HD;
    float y0 = ((v0 - mu) * rstd * gamma[lane]      + beta[lane])      * ub[lane];
    float y1 = ((v1 - mu) * rstd * gamma[lane + 32] + beta[lane + 32]) * ub[lane + 32];
    split_store(fh, fl, ob + lane,      y0);
    split_store(fh, fl, ob + lane + 32, y1);
}

// ---------------------------------------------------------------------------
extern "C" void kernel_launch(void* const* d_in, const int* in_sizes, int n_in,
                              void* d_out, int out_size)
{
    const float *x = nullptr, *attn_mask = nullptr, *cmask = nullptr;
    const float *Wqkuv = nullptr, *Wout = nullptr;
    const float *gamma = nullptr, *beta = nullptr, *cbias = nullptr;
    for (int i = 0; i < n_in; i++) {
        const float* p = (const float*)d_in[i];
        switch (in_sizes[i]) {
            case MROWS * Dd:        x = p; break;
            case Bb * Ll * Ll:      attn_mask = p; break;
            case Bb * Ll:           cmask = p; break;
            case Dd * NQKUV:        Wqkuv = p; break;
            case Dd * Dd:           Wout = p; break;
            case HD:                if (!gamma) gamma = p; else beta = p; break;
            case Hh:                cbias = p; break;
            default: break;
        }
    }
    float* out = (float*)d_out;

    float *qkuv, *attn;
    __nv_bfloat16 *xh, *xl, *wth, *wtl, *fh, *fl, *qh, *ql, *kh, *kl, *vth, *vtl;
    cudaGetSymbolAddress((void**)&qkuv, g_qkuv);
    cudaGetSymbolAddress((void**)&attn, g_attn);
    cudaGetSymbolAddress((void**)&xh,  g_xh);
    cudaGetSymbolAddress((void**)&xl,  g_xl);
    cudaGetSymbolAddress((void**)&wth, g_wth);
    cudaGetSymbolAddress((void**)&wtl, g_wtl);
    cudaGetSymbolAddress((void**)&fh,  g_fh);
    cudaGetSymbolAddress((void**)&fl,  g_fl);
    cudaGetSymbolAddress((void**)&qh,  g_qh);
    cudaGetSymbolAddress((void**)&ql,  g_ql);
    cudaGetSymbolAddress((void**)&kh,  g_kh);
    cudaGetSymbolAddress((void**)&kl,  g_kl);
    cudaGetSymbolAddress((void**)&vth, g_vth);
    cudaGetSymbolAddress((void**)&vtl, g_vtl);

    cudaFuncSetAttribute(gemm_mma<true>,  cudaFuncAttributeMaxDynamicSharedMemorySize, SMEM_MMA);
    cudaFuncSetAttribute(gemm_mma<false>, cudaFuncAttributeMaxDynamicSharedMemorySize, SMEM_MMA);
    cudaFuncSetAttribute(attn_mma, cudaFuncAttributeMaxDynamicSharedMemorySize, A_TOT);

    // 1) split inputs
    split_rows<<<(MROWS * KDIM / 4) / 256, 256>>>(x, xh, xl);
    splitT<<<dim3(NQKUV / 32, KDIM / 32), dim3(32, 8)>>>(Wqkuv, wth, wtl, NQKUV);

    // 2) qkuv = silu(x @ Wqkuv)
    gemm_mma<true><<<dim3(NQKUV / 128, MROWS / 128), 256, SMEM_MMA>>>(
        xh, xl, wth, wtl, qkuv, NQKUV);

    // 3) prep attention operands: RoPE+split q,k; transpose+split v
    rope_split_qk<<<(Bb * Ll * Hh * 32) / 256, 256>>>(qkuv, qh, ql, kh, kl);
    vtrans_split<<<dim3(Ll / 64, Hh, Bb), 256>>>(qkuv, vth, vtl);

    // 4) HMMA attention
    attn_mma<<<dim3(Ll / 128, Hh, Bb), 256, A_TOT>>>(
        qh, ql, kh, kl, vth, vtl, attn_mask, cmask, cbias, attn);

    // 5) LayerNorm(d) + u-gate -> split bf16
    ln_gate_kernel<<<(Bb * Hh * Ll * 32) / 256, 256>>>(attn, qkuv, gamma, beta, fh, fl);

    // 6) out = flat @ Wout
    splitT<<<dim3(Dd / 32, KDIM / 32), dim3(32, 8)>>>(Wout, wth, wtl, Dd);
    gemm_mma<false><<<dim3(Dd / 128, MROWS / 128), 256, SMEM_MMA>>>(
        fh, fl, wth, wtl, out, Dd);
}

// round 5
// speedup vs baseline: 2.6692x; 1.0638x over previous
#include <cuda_runtime.h>
#include <cuda_bf16.h>
#include <math.h>
#include <stdint.h>

#define Bb 4
#define Ll 2048
#define Dd 1024
#define Hh 16
#define HD 64
#define MROWS (Bb*Ll)        // 8192
#define NQKUV (4*Dd)         // 4096
#define KDIM  Dd             // 1024

// ---------------- scratch (device globals; no cudaMalloc allowed) ----------
__device__ float g_qkuv[(size_t)MROWS * NQKUV];                 // 128 MB
__device__ float g_attn[(size_t)Bb*Hh*Ll*HD];                   // 32 MB
__device__ __align__(256) __nv_bfloat16 g_xh[(size_t)MROWS * KDIM];
__device__ __align__(256) __nv_bfloat16 g_xl[(size_t)MROWS * KDIM];
__device__ __align__(256) __nv_bfloat16 g_wth[(size_t)NQKUV * KDIM]; // [N][K]
__device__ __align__(256) __nv_bfloat16 g_wtl[(size_t)NQKUV * KDIM];
__device__ __align__(256) __nv_bfloat16 g_woh[(size_t)Dd * KDIM];    // Wout^T
__device__ __align__(256) __nv_bfloat16 g_wol[(size_t)Dd * KDIM];
__device__ __align__(256) __nv_bfloat16 g_fh[(size_t)MROWS * KDIM];
__device__ __align__(256) __nv_bfloat16 g_fl[(size_t)MROWS * KDIM];
// attention operands, head-major
__device__ __align__(256) __nv_bfloat16 g_qh[(size_t)Bb*Hh*Ll*HD];
__device__ __align__(256) __nv_bfloat16 g_ql[(size_t)Bb*Hh*Ll*HD];
__device__ __align__(256) __nv_bfloat16 g_kh[(size_t)Bb*Hh*Ll*HD];
__device__ __align__(256) __nv_bfloat16 g_kl[(size_t)Bb*Hh*Ll*HD];
__device__ __align__(256) __nv_bfloat16 g_vth[(size_t)Bb*Hh*HD*Ll];  // [b,h,d,L]
__device__ __align__(256) __nv_bfloat16 g_vtl[(size_t)Bb*Hh*HD*Ll];

__device__ __forceinline__ float silu_f(float x) { return x / (1.0f + expf(-x)); }

__device__ __forceinline__ uint32_t smem_u32(const void* p) {
    uint32_t a;
    asm("{ .reg .u64 t; cvta.to.shared.u64 t, %1; cvt.u32.u64 %0, t; }" : "=r"(a) : "l"(p));
    return a;
}

__device__ __forceinline__ void split_store(__nv_bfloat16* h, __nv_bfloat16* l,
                                            size_t idx, float v) {
    __nv_bfloat16 hb = __float2bfloat16(v);
    h[idx] = hb;
    l[idx] = __float2bfloat16(v - __bfloat162float(hb));
}

__device__ __forceinline__ uint32_t pack_bf2(float a, float b) {
    __nv_bfloat162 t = __floats2bfloat162_rn(a, b);
    return *(uint32_t*)&t;
}

// split two floats into packed-hi and packed-lo bf16x2 regs
__device__ __forceinline__ void split2(float a, float b, uint32_t& hi, uint32_t& lo) {
    __nv_bfloat16 ha = __float2bfloat16(a), hb = __float2bfloat16(b);
    hi = (uint32_t)__bfloat16_as_ushort(ha) | ((uint32_t)__bfloat16_as_ushort(hb) << 16);
    lo = pack_bf2(a - __bfloat162float(ha), b - __bfloat162float(hb));
}

// ---------------------------------------------------------------------------
// Split helpers
// ---------------------------------------------------------------------------
__global__ void split_rows(const float* __restrict__ src,
                           __nv_bfloat16* __restrict__ h,
                           __nv_bfloat16* __restrict__ l)
{
    int i = blockIdx.x * blockDim.x + threadIdx.x;
    float4 v = ((const float4*)src)[i];
    float a[4] = {v.x, v.y, v.z, v.w};
    ushort4 ho, lo;
    unsigned short* hp = &ho.x; unsigned short* lp = &lo.x;
    #pragma unroll
    for (int j = 0; j < 4; j++) {
        __nv_bfloat16 hb = __float2bfloat16(a[j]);
        __nv_bfloat16 lb = __float2bfloat16(a[j] - __bfloat162float(hb));
        hp[j] = __bfloat16_as_ushort(hb);
        lp[j] = __bfloat16_as_ushort(lb);
    }
    ((ushort4*)h)[i] = ho;
    ((ushort4*)l)[i] = lo;
}

__global__ void splitT(const float* __restrict__ W,
                       __nv_bfloat16* __restrict__ h,
                       __nv_bfloat16* __restrict__ l, int N)
{
    __shared__ float t[32][33];
    int n0 = blockIdx.x * 32, k0 = blockIdx.y * 32;
    int tx = threadIdx.x, ty = threadIdx.y;
    #pragma unroll
    for (int j = 0; j < 4; j++)
        t[ty + j*8][tx] = W[(size_t)(k0 + ty + j*8) * N + n0 + tx];
    __syncthreads();
    #pragma unroll
    for (int j = 0; j < 4; j++) {
        float v = t[tx][ty + j*8];
        size_t idx = (size_t)(n0 + ty + j*8) * KDIM + k0 + tx;
        split_store(h, l, idx, v);
    }
}

// ---------------------------------------------------------------------------
// mma.sync primitives
// ---------------------------------------------------------------------------
__device__ __forceinline__ void mma_bf16(float* d, const uint32_t* a, const uint32_t* b) {
    asm volatile(
        "mma.sync.aligned.m16n8k16.row.col.f32.bf16.bf16.f32 "
        "{%0,%1,%2,%3}, {%4,%5,%6,%7}, {%8,%9}, {%0,%1,%2,%3};"
        : "+f"(d[0]), "+f"(d[1]), "+f"(d[2]), "+f"(d[3])
        : "r"(a[0]), "r"(a[1]), "r"(a[2]), "r"(a[3]), "r"(b[0]), "r"(b[1]));
}

__device__ __forceinline__ void ldm_x4(uint32_t* r, uint32_t addr) {
    asm volatile("ldmatrix.sync.aligned.m8n8.x4.shared.b16 {%0,%1,%2,%3}, [%4];"
                 : "=r"(r[0]), "=r"(r[1]), "=r"(r[2]), "=r"(r[3]) : "r"(addr));
}

__device__ __forceinline__ void cp16(uint32_t dst, const void* src) {
    asm volatile("cp.async.cg.shared.global [%0], [%1], 16;" :: "r"(dst), "l"(src));
}
__device__ __forceinline__ void cp_commit() {
    asm volatile("cp.async.commit_group;" ::: "memory");
}
__device__ __forceinline__ void cp_wait_all() {
    asm volatile("cp.async.wait_group 0;" ::: "memory");
}

// ---------------------------------------------------------------------------
// Projection GEMM (unchanged)
// ---------------------------------------------------------------------------
#define LDT 40
#define TSTG (128 * LDT)
#define STAGE_E (4 * TSTG)
#define SMEM_MMA (2 * STAGE_E * 2)

template<bool SILU>
__global__ __launch_bounds__(256, 2) void gemm_mma(
    const __nv_bfloat16* __restrict__ Ah, const __nv_bfloat16* __restrict__ Al,
    const __nv_bfloat16* __restrict__ Bh, const __nv_bfloat16* __restrict__ Bl,
    float* __restrict__ C, int Ndim)
{
    extern __shared__ __align__(128) char sm[];
    const uint32_t smb = smem_u32(sm);
    const int tid = threadIdx.x;
    const int lane = tid & 31, wid = tid >> 5;
    const int wm = wid >> 1, wn = wid & 1;
    const int m0 = blockIdx.y * 128, n0 = blockIdx.x * 128;

    const __nv_bfloat16* gsrc[4] = {
        Ah + (size_t)m0 * KDIM, Al + (size_t)m0 * KDIM,
        Bh + (size_t)n0 * KDIM, Bl + (size_t)n0 * KDIM };

    auto load_stage = [&](int s, int k0) {
        #pragma unroll
        for (int mmat = 0; mmat < 4; mmat++) {
            uint32_t tbase = smb + (uint32_t)(s * STAGE_E + mmat * TSTG) * 2;
            #pragma unroll
            for (int i = 0; i < 2; i++) {
                int chunk = tid + i * 256;
                int row = chunk >> 2, seg = chunk & 3;
                cp16(tbase + (uint32_t)(row * LDT + seg * 8) * 2,
                     gsrc[mmat] + (size_t)row * KDIM + k0 + seg * 8);
            }
        }
        cp_commit();
    };

    float acc[2][8][4];
    #pragma unroll
    for (int i = 0; i < 2; i++)
        #pragma unroll
        for (int j = 0; j < 8; j++)
            #pragma unroll
            for (int q = 0; q < 4; q++) acc[i][j][q] = 0.0f;

    const int NS = KDIM / 32;
    load_stage(0, 0);

    const int arow = wm * 32 + (lane & 15);
    const int acol = (lane >> 4) * 8;
    const int brow = wn * 64 + (lane & 7) + (lane >> 4) * 8;
    const int bcol = ((lane >> 3) & 1) * 8;

    for (int st = 0; st < NS; st++) {
        if (st + 1 < NS) {
            load_stage((st + 1) & 1, (st + 1) * 32);
            asm volatile("cp.async.wait_group 1;" ::: "memory");
        } else {
            cp_wait_all();
        }
        __syncthreads();

        uint32_t sb = smb + (uint32_t)((st & 1) * STAGE_E) * 2;
        uint32_t ah_b = sb;
        uint32_t al_b = sb + (uint32_t)TSTG * 2;
        uint32_t bh_b = sb + (uint32_t)(2 * TSTG) * 2;
        uint32_t bl_b = sb + (uint32_t)(3 * TSTG) * 2;

        #pragma unroll
        for (int ks = 0; ks < 32; ks += 16) {
            uint32_t ra_h[2][4], ra_l[2][4];
            #pragma unroll
            for (int mt = 0; mt < 2; mt++) {
                uint32_t off = (uint32_t)((arow + mt * 16) * LDT + ks + acol) * 2;
                ldm_x4(ra_h[mt], ah_b + off);
                ldm_x4(ra_l[mt], al_b + off);
            }
            #pragma unroll
            for (int bhalf = 0; bhalf < 2; bhalf++) {
                uint32_t rb_h[2][4], rb_l[2][4];
                #pragma unroll
                for (int bt = 0; bt < 2; bt++) {
                    uint32_t off = (uint32_t)((brow + bhalf * 32 + bt * 16) * LDT
                                              + ks + bcol) * 2;
                    ldm_x4(rb_h[bt], bh_b + off);
                    ldm_x4(rb_l[bt], bl_b + off);
                }
                #pragma unroll
                for (int mt = 0; mt < 2; mt++)
                    #pragma unroll
                    for (int nt = 0; nt < 4; nt++) {
                        float* d = acc[mt][bhalf * 4 + nt];
                        const uint32_t* bhf = &rb_h[nt >> 1][(nt & 1) * 2];
                        const uint32_t* blf = &rb_l[nt >> 1][(nt & 1) * 2];
                        mma_bf16(d, ra_h[mt], bhf);
                        mma_bf16(d, ra_h[mt], blf);
                        mma_bf16(d, ra_l[mt], bhf);
                    }
            }
        }
        __syncthreads();
    }

    const int mbase = m0 + wm * 32 + (lane >> 2);
    const int nbase = n0 + wn * 64 + (lane & 3) * 2;
    #pragma unroll
    for (int mt = 0; mt < 2; mt++) {
        #pragma unroll
        for (int nt = 0; nt < 8; nt++) {
            float v0 = acc[mt][nt][0], v1 = acc[mt][nt][1];
            float v2 = acc[mt][nt][2], v3 = acc[mt][nt][3];
            if (SILU) { v0 = silu_f(v0); v1 = silu_f(v1); v2 = silu_f(v2); v3 = silu_f(v3); }
            int r = mbase + mt * 16, c = nbase + nt * 8;
            *(float2*)(C + (size_t)r * Ndim + c) = make_float2(v0, v1);
            *(float2*)(C + (size_t)(r + 8) * Ndim + c) = make_float2(v2, v3);
        }
    }
}

// ---------------------------------------------------------------------------
// Prep 1: RoPE + hi/lo split q,k -> head-major [b,h,l,64]
// ---------------------------------------------------------------------------
__global__ void rope_split_qk(const float* __restrict__ qkuv,
    __nv_bfloat16* __restrict__ qh, __nv_bfloat16* __restrict__ ql,
    __nv_bfloat16* __restrict__ kh, __nv_bfloat16* __restrict__ kl)
{
    int tid = blockIdx.x * blockDim.x + threadIdx.x;
    int i = tid & 31;
    int h = (tid >> 5) & (Hh - 1);
    int l = (tid >> 9) & (Ll - 1);
    int b = tid >> 20;
    float inv_freq = expf(-(float)i * 0.28782313662425583f);
    float theta = (float)l * inv_freq;
    float c = cosf(theta), s = sinf(theta);
    const float* base = qkuv + ((size_t)(b * Ll + l)) * NQKUV + h * HD;
    float q0 = base[i], q1 = base[i + 32];
    float k0 = base[Dd + i], k1 = base[Dd + i + 32];
    float qr0 = q0 * c - q1 * s, qr1 = q1 * c + q0 * s;
    float kr0 = k0 * c - k1 * s, kr1 = k1 * c + k0 * s;
    size_t o = ((size_t)((b * Hh + h) * Ll) + l) * HD;
    split_store(qh, ql, o + i,      qr0);
    split_store(qh, ql, o + i + 32, qr1);
    split_store(kh, kl, o + i,      kr0);
    split_store(kh, kl, o + i + 32, kr1);
}

// ---------------------------------------------------------------------------
// Prep 2: V transpose + split -> [b,h,d,L]
// ---------------------------------------------------------------------------
__global__ void vtrans_split(const float* __restrict__ qkuv,
    __nv_bfloat16* __restrict__ vth, __nv_bfloat16* __restrict__ vtl)
{
    __shared__ float ts[64][65];
    int b = blockIdx.z, h = blockIdx.y, l0 = blockIdx.x * 64;
    int tid = threadIdx.x;
    const float* vsrc = qkuv + (size_t)(b * Ll + l0) * NQKUV + 2 * Dd + h * HD;
    #pragma unroll
    for (int k = 0; k < 4; k++) {
        int c = tid + k * 256;
        int r = c >> 4, c4 = c & 15;
        float4 v = *(const float4*)(vsrc + (size_t)r * NQKUV + c4 * 4);
        ts[r][c4*4+0] = v.x; ts[r][c4*4+1] = v.y;
        ts[r][c4*4+2] = v.z; ts[r][c4*4+3] = v.w;
    }
    __syncthreads();
    size_t obase = ((size_t)((b * Hh + h) * HD)) * Ll + l0;
    #pragma unroll
    for (int k = 0; k < 4; k++) {
        int c = tid + k * 256;
        int d = c >> 4, j4 = c & 15;
        ushort4 ho, lo;
        unsigned short* hp = &ho.x; unsigned short* lp = &lo.x;
        #pragma unroll
        for (int j = 0; j < 4; j++) {
            float v = ts[j4*4 + j][d];
            __nv_bfloat16 hb = __float2bfloat16(v);
            hp[j] = __bfloat16_as_ushort(hb);
            lp[j] = __bfloat16_as_ushort(__float2bfloat16(v - __bfloat162float(hb)));
        }
        *(ushort4*)(vth + obase + (size_t)d * Ll + j4 * 4) = ho;
        *(ushort4*)(vtl + obase + (size_t)d * Ll + j4 * 4) = lo;
    }
}

// ---------------------------------------------------------------------------
// HMMA attention, register-resident S. 8 warps x 16 q-rows, k-tile 128.
// Double-buffered K/V, single sync per tile, epilogue fused into SV loop.
// ---------------------------------------------------------------------------
#define ALD 72       // q/k smem pitch (bf16): 144B rows, conflict-free
#define SLDV 136     // vT smem pitch (bf16): 272B rows
#define AQ_H 0
#define AQ_L 18432
#define ST_BASE 36864
#define ST_SIZE 71680        // k hi/lo (2x18432) + v hi/lo (2x17408)
#define ST_KH 0
#define ST_KL 18432
#define ST_VH 36864
#define ST_VL 54272
#define A_TOT (ST_BASE + 2 * ST_SIZE)   // 180224

__global__ __launch_bounds__(256) void attn_reg(
    const __nv_bfloat16* __restrict__ qh_g, const __nv_bfloat16* __restrict__ ql_g,
    const __nv_bfloat16* __restrict__ kh_g, const __nv_bfloat16* __restrict__ kl_g,
    const __nv_bfloat16* __restrict__ vth_g, const __nv_bfloat16* __restrict__ vtl_g,
    const float* __restrict__ attn_mask, const float* __restrict__ cmask,
    const float* __restrict__ cbias, float* __restrict__ out)
{
    extern __shared__ __align__(128) char sm[];
    const uint32_t smb = smem_u32(sm);
    const int tid = threadIdx.x;
    const int lane = tid & 31, wid = tid >> 5;
    const int b = blockIdx.z, h = blockIdx.y;
    const int l0 = blockIdx.x * 128;
    const size_t bh = (size_t)(b * Hh + h);
    const float cb = cbias[h];

    const __nv_bfloat16* qh_p = qh_g + (bh * Ll + l0) * HD;
    const __nv_bfloat16* ql_p = ql_g + (bh * Ll + l0) * HD;
    const __nv_bfloat16* kh_p = kh_g + bh * Ll * HD;
    const __nv_bfloat16* kl_p = kl_g + bh * Ll * HD;
    const __nv_bfloat16* vth_p = vth_g + bh * HD * Ll;
    const __nv_bfloat16* vtl_p = vtl_g + bh * HD * Ll;

    auto load_kv = [&](int m0k, int p) {
        uint32_t base = smb + ST_BASE + (uint32_t)p * ST_SIZE;
        #pragma unroll
        for (int i = 0; i < 4; i++) {           // k: 128 rows x 128B
            int c = tid + i * 256;
            int row = c >> 3, seg = c & 7;
            uint32_t d = (uint32_t)(row * 144 + seg * 16);
            size_t g = (size_t)(m0k + row) * HD + seg * 8;
            cp16(base + ST_KH + d, kh_p + g);
            cp16(base + ST_KL + d, kl_p + g);
        }
        #pragma unroll
        for (int i = 0; i < 4; i++) {           // vT: 64 rows x 256B
            int c = tid + i * 256;
            int row = c >> 4, seg = c & 15;
            uint32_t d = (uint32_t)(row * 272 + seg * 16);
            size_t g = (size_t)row * Ll + m0k + seg * 8;
            cp16(base + ST_VH + d, vth_p + g);
            cp16(base + ST_VL + d, vtl_p + g);
        }
        cp_commit();
    };

    // load q tile (hi/lo)
    #pragma unroll
    for (int i = 0; i < 4; i++) {
        int c = tid + i * 256;
        int row = c >> 3, seg = c & 7;
        uint32_t d = (uint32_t)(row * 144 + seg * 16);
        size_t g = (size_t)row * HD + seg * 8;
        cp16(smb + AQ_H + d, qh_p + g);
        cp16(smb + AQ_L + d, ql_p + g);
    }
    cp_commit();
    load_kv(0, 0);
    cp_wait_all();
    __syncthreads();

    // q fragments -> registers (once)
    const int brow = (lane & 7) + ((lane >> 4) << 3);
    const int bcol = ((lane >> 3) & 1) * 8;
    uint32_t qfh[4][4], qfl[4][4];
    {
        uint32_t roff = (uint32_t)((wid * 16 + (lane & 15)) * ALD) * 2;
        uint32_t coff = (uint32_t)((lane >> 4) * 8) * 2;
        #pragma unroll
        for (int ks = 0; ks < 4; ks++) {
            uint32_t off = roff + (uint32_t)(ks * 16) * 2 + coff;
            ldm_x4(qfh[ks], smb + AQ_H + off);
            ldm_x4(qfl[ks], smb + AQ_L + off);
        }
    }

    float oacc[8][4];
    #pragma unroll
    for (int j = 0; j < 8; j++)
        #pragma unroll
        for (int q = 0; q < 4; q++) oacc[j][q] = 0.0f;

    const int rl = lane >> 2;                  // row within 16-row group (0..7)
    const int rg0 = l0 + wid * 16 + rl;        // global q row
    const int ct0 = (lane & 3) * 2;            // col pair base

    for (int t = 0; t < 16; t++) {
        const int p = t & 1;
        const int m0 = t * 128;
        if (t > 0) { cp_wait_all(); __syncthreads(); }
        if (t + 1 < 16) load_kv(m0 + 128, 1 - p);

        const uint32_t skh = smb + ST_BASE + (uint32_t)p * ST_SIZE + ST_KH;
        const uint32_t skl = skh + (ST_KL - ST_KH);
        const uint32_t svh = smb + ST_BASE + (uint32_t)p * ST_SIZE + ST_VH;
        const uint32_t svl = svh + (ST_VL - ST_VH);

        // ---- QK: S[16 rows][128 cols] in registers, 3-term ----
        float sacc[16][4];
        #pragma unroll
        for (int j = 0; j < 16; j++)
            #pragma unroll
            for (int q = 0; q < 4; q++) sacc[j][q] = 0.0f;

        #pragma unroll
        for (int ks = 0; ks < 4; ks++) {
            #pragma unroll
            for (int nbq = 0; nbq < 8; nbq++) {
                uint32_t kh4[4], kl4[4];
                uint32_t off = (uint32_t)((nbq * 16 + brow) * ALD + ks * 16 + bcol) * 2;
                ldm_x4(kh4, skh + off);
                ldm_x4(kl4, skl + off);
                #pragma unroll
                for (int half = 0; half < 2; half++) {
                    int j = nbq * 2 + half;
                    mma_bf16(sacc[j], qfh[ks], &kh4[half * 2]);
                    mma_bf16(sacc[j], qfh[ks], &kl4[half * 2]);
                    mma_bf16(sacc[j], qfl[ks], &kh4[half * 2]);
                }
            }
        }

        // ---- SV with fused epilogue: per k16 step, convert 2 S-blocks ----
        #pragma unroll
        for (int s = 0; s < 8; s++) {
            uint32_t ah[4], al[4];
            #pragma unroll
            for (int e = 0; e < 2; e++) {
                int j = 2 * s + e;
                int cl = j * 8 + ct0;
                float2 cmv = *(const float2*)(cmask + b * Ll + m0 + cl);
                const float* mrow = attn_mask + ((size_t)b * Ll + rg0) * Ll + m0 + cl;
                float2 mk0 = *(const float2*)mrow;
                float2 mk1 = *(const float2*)(mrow + (size_t)8 * Ll);
                float x0 = sacc[j][0] * 0.125f + cmv.x * cb;
                float x1 = sacc[j][1] * 0.125f + cmv.y * cb;
                float x2 = sacc[j][2] * 0.125f + cmv.x * cb;
                float x3 = sacc[j][3] * 0.125f + cmv.y * cb;
                float s0 = __fdividef(x0, 1.0f + __expf(-x0)) * mk0.x;
                float s1 = __fdividef(x1, 1.0f + __expf(-x1)) * mk0.y;
                float s2 = __fdividef(x2, 1.0f + __expf(-x2)) * mk1.x;
                float s3 = __fdividef(x3, 1.0f + __expf(-x3)) * mk1.y;
                split2(s0, s1, ah[e * 2 + 0], al[e * 2 + 0]);
                split2(s2, s3, ah[e * 2 + 1], al[e * 2 + 1]);
            }
            uint32_t fvh[4][4], fvl[4][4];
            #pragma unroll
            for (int dv = 0; dv < 4; dv++) {
                uint32_t off = (uint32_t)((dv * 16 + brow) * SLDV + s * 16 + bcol) * 2;
                ldm_x4(fvh[dv], svh + off);
                ldm_x4(fvl[dv], svl + off);
            }
            #pragma unroll
            for (int j = 0; j < 8; j++) {
                const uint32_t* bf = &fvh[j >> 1][(j & 1) * 2];
                const uint32_t* bl = &fvl[j >> 1][(j & 1) * 2];
                mma_bf16(oacc[j], ah, bf);
                mma_bf16(oacc[j], ah, bl);
                mma_bf16(oacc[j], al, bf);
            }
        }
    }

    // ---- write O: [b,h,l,d] fp32 ----
    #pragma unroll
    for (int j = 0; j < 8; j++) {
        int c = j * 8 + ct0;
        *(float2*)(out + (bh * Ll + rg0) * HD + c) = make_float2(oacc[j][0], oacc[j][1]);
        *(float2*)(out + (bh * Ll + rg0 + 8) * HD + c) = make_float2(oacc[j][2], oacc[j][3]);
    }
}

// ---------------------------------------------------------------------------
// LayerNorm(d) + u-gate -> split bf16 (B,L,D)
// ---------------------------------------------------------------------------
__global__ void ln_gate_kernel(
    const float* __restrict__ attn, const float* __restrict__ qkuv,
    const float* __restrict__ gamma, const float* __restrict__ beta,
    __nv_bfloat16* __restrict__ fh, __nv_bfloat16* __restrict__ fl)
{
    int warp = (blockIdx.x * blockDim.x + threadIdx.x) >> 5;
    int lane = threadIdx.x & 31;
    int l = warp & (Ll - 1);
    int h = (warp >> 11) & (Hh - 1);
    int b = warp >> 15;
    const float* row = attn + (size_t)warp * HD;
    float v0 = row[lane], v1 = row[lane + 32];
    float s = v0 + v1, sq = v0 * v0 + v1 * v1;
    #pragma unroll
    for (int o = 16; o > 0; o >>= 1) {
        s  += __shfl_xor_sync(0xFFFFFFFFu, s,  o);
        sq += __shfl_xor_sync(0xFFFFFFFFu, sq, o);
    }
    float mu = s * (1.0f / 64.0f);
    float var = sq * (1.0f / 64.0f) - mu * mu;
    float rstd = rsqrtf(var + 1e-5f);
    const float* ub = qkuv + ((size_t)(b * Ll + l)) * NQKUV + 3 * Dd + h * HD;
    size_t ob = ((size_t)(b * Ll + l)) * Dd + h * HD;
    float y0 = ((v0 - mu) * rstd * gamma[lane]      + beta[lane])      * ub[lane];
    float y1 = ((v1 - mu) * rstd * gamma[lane + 32] + beta[lane + 32]) * ub[lane + 32];
    split_store(fh, fl, ob + lane,      y0);
    split_store(fh, fl, ob + lane + 32, y1);
}

// ---------------------------------------------------------------------------
extern "C" void kernel_launch(void* const* d_in, const int* in_sizes, int n_in,
                              void* d_out, int out_size)
{
    const float *x = nullptr, *attn_mask = nullptr, *cmask = nullptr;
    const float *Wqkuv = nullptr, *Wout = nullptr;
    const float *gamma = nullptr, *beta = nullptr, *cbias = nullptr;
    for (int i = 0; i < n_in; i++) {
        const float* p = (const float*)d_in[i];
        switch (in_sizes[i]) {
            case MROWS * Dd:        x = p; break;
            case Bb * Ll * Ll:      attn_mask = p; break;
            case Bb * Ll:           cmask = p; break;
            case Dd * NQKUV:        Wqkuv = p; break;
            case Dd * Dd:           Wout = p; break;
            case HD:                if (!gamma) gamma = p; else beta = p; break;
            case Hh:                cbias = p; break;
            default: break;
        }
    }
    float* out = (float*)d_out;

    float *qkuv, *attn;
    __nv_bfloat16 *xh, *xl, *wth, *wtl, *woh, *wol, *fh, *fl;
    __nv_bfloat16 *qh, *ql, *kh, *kl, *vth, *vtl;
    cudaGetSymbolAddress((void**)&qkuv, g_qkuv);
    cudaGetSymbolAddress((void**)&attn, g_attn);
    cudaGetSymbolAddress((void**)&xh,  g_xh);
    cudaGetSymbolAddress((void**)&xl,  g_xl);
    cudaGetSymbolAddress((void**)&wth, g_wth);
    cudaGetSymbolAddress((void**)&wtl, g_wtl);
    cudaGetSymbolAddress((void**)&woh, g_woh);
    cudaGetSymbolAddress((void**)&wol, g_wol);
    cudaGetSymbolAddress((void**)&fh,  g_fh);
    cudaGetSymbolAddress((void**)&fl,  g_fl);
    cudaGetSymbolAddress((void**)&qh,  g_qh);
    cudaGetSymbolAddress((void**)&ql,  g_ql);
    cudaGetSymbolAddress((void**)&kh,  g_kh);
    cudaGetSymbolAddress((void**)&kl,  g_kl);
    cudaGetSymbolAddress((void**)&vth, g_vth);
    cudaGetSymbolAddress((void**)&vtl, g_vtl);

    cudaFuncSetAttribute(gemm_mma<true>,  cudaFuncAttributeMaxDynamicSharedMemorySize, SMEM_MMA);
    cudaFuncSetAttribute(gemm_mma<false>, cudaFuncAttributeMaxDynamicSharedMemorySize, SMEM_MMA);
    cudaFuncSetAttribute(attn_reg, cudaFuncAttributeMaxDynamicSharedMemorySize, A_TOT);

    // 1) splits (Wout early so gemm_mma<true> is launch #4 -> profiled slot)
    split_rows<<<(MROWS * KDIM / 4) / 256, 256>>>(x, xh, xl);
    splitT<<<dim3(NQKUV / 32, KDIM / 32), dim3(32, 8)>>>(Wqkuv, wth, wtl, NQKUV);
    splitT<<<dim3(Dd / 32, KDIM / 32), dim3(32, 8)>>>(Wout, woh, wol, Dd);

    // 2) qkuv = silu(x @ Wqkuv)
    gemm_mma<true><<<dim3(NQKUV / 128, MROWS / 128), 256, SMEM_MMA>>>(
        xh, xl, wth, wtl, qkuv, NQKUV);

    // 3) prep attention operands
    rope_split_qk<<<(Bb * Ll * Hh * 32) / 256, 256>>>(qkuv, qh, ql, kh, kl);
    vtrans_split<<<dim3(Ll / 64, Hh, Bb), 256>>>(qkuv, vth, vtl);

    // 4) register-S HMMA attention
    attn_reg<<<dim3(Ll / 128, Hh, Bb), 256, A_TOT>>>(
        qh, ql, kh, kl, vth, vtl, attn_mask, cmask, cbias, attn);

    // 5) LayerNorm(d) + u-gate -> split bf16
    ln_gate_kernel<<<(Bb * Hh * Ll * 32) / 256, 256>>>(attn, qkuv, gamma, beta, fh, fl);

    // 6) out = flat @ Wout
    gemm_mma<false><<<dim3(Dd / 128, MROWS / 128), 256, SMEM_MMA>>>(
        fh, fl, woh, wol, out, Dd);
}

// round 6
// speedup vs baseline: 2.8730x; 1.0764x over previous
#include <cuda_runtime.h>
#include <cuda_bf16.h>
#include <math.h>
#include <stdint.h>

#define Bb 4
#define Ll 2048
#define Dd 1024
#define Hh 16
#define HD 64
#define MROWS (Bb*Ll)        // 8192
#define NQKUV (4*Dd)         // 4096
#define KDIM  Dd             // 1024

// ---------------- scratch (device globals; no cudaMalloc allowed) ----------
__device__ float g_qkuv[(size_t)MROWS * NQKUV];                 // 128 MB
__device__ float g_attn[(size_t)Bb*Hh*Ll*HD];                   // 32 MB
__device__ __align__(256) __nv_bfloat16 g_xh[(size_t)MROWS * KDIM];
__device__ __align__(256) __nv_bfloat16 g_xl[(size_t)MROWS * KDIM];
__device__ __align__(256) __nv_bfloat16 g_wth[(size_t)NQKUV * KDIM]; // [N][K]
__device__ __align__(256) __nv_bfloat16 g_wtl[(size_t)NQKUV * KDIM];
__device__ __align__(256) __nv_bfloat16 g_woh[(size_t)Dd * KDIM];    // Wout^T
__device__ __align__(256) __nv_bfloat16 g_wol[(size_t)Dd * KDIM];
__device__ __align__(256) __nv_bfloat16 g_fh[(size_t)MROWS * KDIM];
__device__ __align__(256) __nv_bfloat16 g_fl[(size_t)MROWS * KDIM];
// attention operands, head-major
__device__ __align__(256) __nv_bfloat16 g_qh[(size_t)Bb*Hh*Ll*HD];
__device__ __align__(256) __nv_bfloat16 g_ql[(size_t)Bb*Hh*Ll*HD];
__device__ __align__(256) __nv_bfloat16 g_kh[(size_t)Bb*Hh*Ll*HD];
__device__ __align__(256) __nv_bfloat16 g_kl[(size_t)Bb*Hh*Ll*HD];
__device__ __align__(256) __nv_bfloat16 g_vth[(size_t)Bb*Hh*HD*Ll];  // [b,h,d,L]
__device__ __align__(256) __nv_bfloat16 g_vtl[(size_t)Bb*Hh*HD*Ll];

__device__ __forceinline__ float silu_f(float x) { return x / (1.0f + expf(-x)); }

__device__ __forceinline__ uint32_t smem_u32(const void* p) {
    uint32_t a;
    asm("{ .reg .u64 t; cvta.to.shared.u64 t, %1; cvt.u32.u64 %0, t; }" : "=r"(a) : "l"(p));
    return a;
}

__device__ __forceinline__ void split_store(__nv_bfloat16* h, __nv_bfloat16* l,
                                            size_t idx, float v) {
    __nv_bfloat16 hb = __float2bfloat16(v);
    h[idx] = hb;
    l[idx] = __float2bfloat16(v - __bfloat162float(hb));
}

__device__ __forceinline__ uint32_t pack_bf2(float a, float b) {
    __nv_bfloat162 t = __floats2bfloat162_rn(a, b);
    return *(uint32_t*)&t;
}

__device__ __forceinline__ void split2(float a, float b, uint32_t& hi, uint32_t& lo) {
    __nv_bfloat16 ha = __float2bfloat16(a), hb = __float2bfloat16(b);
    hi = (uint32_t)__bfloat16_as_ushort(ha) | ((uint32_t)__bfloat16_as_ushort(hb) << 16);
    lo = pack_bf2(a - __bfloat162float(ha), b - __bfloat162float(hb));
}

// ---------------------------------------------------------------------------
// Split helpers
// ---------------------------------------------------------------------------
__global__ void split_rows(const float* __restrict__ src,
                           __nv_bfloat16* __restrict__ h,
                           __nv_bfloat16* __restrict__ l)
{
    int i = blockIdx.x * blockDim.x + threadIdx.x;
    float4 v = ((const float4*)src)[i];
    float a[4] = {v.x, v.y, v.z, v.w};
    ushort4 ho, lo;
    unsigned short* hp = &ho.x; unsigned short* lp = &lo.x;
    #pragma unroll
    for (int j = 0; j < 4; j++) {
        __nv_bfloat16 hb = __float2bfloat16(a[j]);
        __nv_bfloat16 lb = __float2bfloat16(a[j] - __bfloat162float(hb));
        hp[j] = __bfloat16_as_ushort(hb);
        lp[j] = __bfloat16_as_ushort(lb);
    }
    ((ushort4*)h)[i] = ho;
    ((ushort4*)l)[i] = lo;
}

__global__ void splitT(const float* __restrict__ W,
                       __nv_bfloat16* __restrict__ h,
                       __nv_bfloat16* __restrict__ l, int N)
{
    __shared__ float t[32][33];
    int n0 = blockIdx.x * 32, k0 = blockIdx.y * 32;
    int tx = threadIdx.x, ty = threadIdx.y;
    #pragma unroll
    for (int j = 0; j < 4; j++)
        t[ty + j*8][tx] = W[(size_t)(k0 + ty + j*8) * N + n0 + tx];
    __syncthreads();
    #pragma unroll
    for (int j = 0; j < 4; j++) {
        float v = t[tx][ty + j*8];
        size_t idx = (size_t)(n0 + ty + j*8) * KDIM + k0 + tx;
        split_store(h, l, idx, v);
    }
}

// ---------------------------------------------------------------------------
// mma.sync primitives
// ---------------------------------------------------------------------------
__device__ __forceinline__ void mma_bf16(float* d, const uint32_t* a, const uint32_t* b) {
    asm volatile(
        "mma.sync.aligned.m16n8k16.row.col.f32.bf16.bf16.f32 "
        "{%0,%1,%2,%3}, {%4,%5,%6,%7}, {%8,%9}, {%0,%1,%2,%3};"
        : "+f"(d[0]), "+f"(d[1]), "+f"(d[2]), "+f"(d[3])
        : "r"(a[0]), "r"(a[1]), "r"(a[2]), "r"(a[3]), "r"(b[0]), "r"(b[1]));
}

__device__ __forceinline__ void ldm_x4(uint32_t* r, uint32_t addr) {
    asm volatile("ldmatrix.sync.aligned.m8n8.x4.shared.b16 {%0,%1,%2,%3}, [%4];"
                 : "=r"(r[0]), "=r"(r[1]), "=r"(r[2]), "=r"(r[3]) : "r"(addr));
}

__device__ __forceinline__ void cp16(uint32_t dst, const void* src) {
    asm volatile("cp.async.cg.shared.global [%0], [%1], 16;" :: "r"(dst), "l"(src));
}
__device__ __forceinline__ void cp_commit() {
    asm volatile("cp.async.commit_group;" ::: "memory");
}
__device__ __forceinline__ void cp_wait_all() {
    asm volatile("cp.async.wait_group 0;" ::: "memory");
}

// ---------------------------------------------------------------------------
// Projection GEMM — single sync per K-stage
// ---------------------------------------------------------------------------
#define LDT 40
#define TSTG (128 * LDT)
#define STAGE_E (4 * TSTG)
#define SMEM_MMA (2 * STAGE_E * 2)

template<bool SILU>
__global__ __launch_bounds__(256, 2) void gemm_mma(
    const __nv_bfloat16* __restrict__ Ah, const __nv_bfloat16* __restrict__ Al,
    const __nv_bfloat16* __restrict__ Bh, const __nv_bfloat16* __restrict__ Bl,
    float* __restrict__ C, int Ndim)
{
    extern __shared__ __align__(128) char sm[];
    const uint32_t smb = smem_u32(sm);
    const int tid = threadIdx.x;
    const int lane = tid & 31, wid = tid >> 5;
    const int wm = wid >> 1, wn = wid & 1;
    const int m0 = blockIdx.y * 128, n0 = blockIdx.x * 128;

    const __nv_bfloat16* gsrc[4] = {
        Ah + (size_t)m0 * KDIM, Al + (size_t)m0 * KDIM,
        Bh + (size_t)n0 * KDIM, Bl + (size_t)n0 * KDIM };

    auto load_stage = [&](int s, int k0) {
        #pragma unroll
        for (int mmat = 0; mmat < 4; mmat++) {
            uint32_t tbase = smb + (uint32_t)(s * STAGE_E + mmat * TSTG) * 2;
            #pragma unroll
            for (int i = 0; i < 2; i++) {
                int chunk = tid + i * 256;
                int row = chunk >> 2, seg = chunk & 3;
                cp16(tbase + (uint32_t)(row * LDT + seg * 8) * 2,
                     gsrc[mmat] + (size_t)row * KDIM + k0 + seg * 8);
            }
        }
        cp_commit();
    };

    float acc[2][8][4];
    #pragma unroll
    for (int i = 0; i < 2; i++)
        #pragma unroll
        for (int j = 0; j < 8; j++)
            #pragma unroll
            for (int q = 0; q < 4; q++) acc[i][j][q] = 0.0f;

    const int NS = KDIM / 32;
    load_stage(0, 0);

    const int arow = wm * 32 + (lane & 15);
    const int acol = (lane >> 4) * 8;
    const int brow = wn * 64 + (lane & 7) + (lane >> 4) * 8;
    const int bcol = ((lane >> 3) & 1) * 8;

    for (int st = 0; st < NS; st++) {
        cp_wait_all();
        __syncthreads();
        // all warps are done reading buffer (st+1)&1 (compute st-1); safe to refill
        if (st + 1 < NS) load_stage((st + 1) & 1, (st + 1) * 32);

        uint32_t sb = smb + (uint32_t)((st & 1) * STAGE_E) * 2;
        uint32_t ah_b = sb;
        uint32_t al_b = sb + (uint32_t)TSTG * 2;
        uint32_t bh_b = sb + (uint32_t)(2 * TSTG) * 2;
        uint32_t bl_b = sb + (uint32_t)(3 * TSTG) * 2;

        #pragma unroll
        for (int ks = 0; ks < 32; ks += 16) {
            uint32_t ra_h[2][4], ra_l[2][4];
            #pragma unroll
            for (int mt = 0; mt < 2; mt++) {
                uint32_t off = (uint32_t)((arow + mt * 16) * LDT + ks + acol) * 2;
                ldm_x4(ra_h[mt], ah_b + off);
                ldm_x4(ra_l[mt], al_b + off);
            }
            #pragma unroll
            for (int bhalf = 0; bhalf < 2; bhalf++) {
                uint32_t rb_h[2][4], rb_l[2][4];
                #pragma unroll
                for (int bt = 0; bt < 2; bt++) {
                    uint32_t off = (uint32_t)((brow + bhalf * 32 + bt * 16) * LDT
                                              + ks + bcol) * 2;
                    ldm_x4(rb_h[bt], bh_b + off);
                    ldm_x4(rb_l[bt], bl_b + off);
                }
                #pragma unroll
                for (int mt = 0; mt < 2; mt++)
                    #pragma unroll
                    for (int nt = 0; nt < 4; nt++) {
                        float* d = acc[mt][bhalf * 4 + nt];
                        const uint32_t* bhf = &rb_h[nt >> 1][(nt & 1) * 2];
                        const uint32_t* blf = &rb_l[nt >> 1][(nt & 1) * 2];
                        mma_bf16(d, ra_h[mt], bhf);
                        mma_bf16(d, ra_h[mt], blf);
                        mma_bf16(d, ra_l[mt], bhf);
                    }
            }
        }
    }

    const int mbase = m0 + wm * 32 + (lane >> 2);
    const int nbase = n0 + wn * 64 + (lane & 3) * 2;
    #pragma unroll
    for (int mt = 0; mt < 2; mt++) {
        #pragma unroll
        for (int nt = 0; nt < 8; nt++) {
            float v0 = acc[mt][nt][0], v1 = acc[mt][nt][1];
            float v2 = acc[mt][nt][2], v3 = acc[mt][nt][3];
            if (SILU) { v0 = silu_f(v0); v1 = silu_f(v1); v2 = silu_f(v2); v3 = silu_f(v3); }
            int r = mbase + mt * 16, c = nbase + nt * 8;
            *(float2*)(C + (size_t)r * Ndim + c) = make_float2(v0, v1);
            *(float2*)(C + (size_t)(r + 8) * Ndim + c) = make_float2(v2, v3);
        }
    }
}

// ---------------------------------------------------------------------------
// Prep 1: RoPE + hi/lo split q,k -> head-major [b,h,l,64]
// ---------------------------------------------------------------------------
__global__ void rope_split_qk(const float* __restrict__ qkuv,
    __nv_bfloat16* __restrict__ qh, __nv_bfloat16* __restrict__ ql,
    __nv_bfloat16* __restrict__ kh, __nv_bfloat16* __restrict__ kl)
{
    int tid = blockIdx.x * blockDim.x + threadIdx.x;
    int i = tid & 31;
    int h = (tid >> 5) & (Hh - 1);
    int l = (tid >> 9) & (Ll - 1);
    int b = tid >> 20;
    float inv_freq = expf(-(float)i * 0.28782313662425583f);
    float theta = (float)l * inv_freq;
    float c = cosf(theta), s = sinf(theta);
    const float* base = qkuv + ((size_t)(b * Ll + l)) * NQKUV + h * HD;
    float q0 = base[i], q1 = base[i + 32];
    float k0 = base[Dd + i], k1 = base[Dd + i + 32];
    float qr0 = q0 * c - q1 * s, qr1 = q1 * c + q0 * s;
    float kr0 = k0 * c - k1 * s, kr1 = k1 * c + k0 * s;
    size_t o = ((size_t)((b * Hh + h) * Ll) + l) * HD;
    split_store(qh, ql, o + i,      qr0);
    split_store(qh, ql, o + i + 32, qr1);
    split_store(kh, kl, o + i,      kr0);
    split_store(kh, kl, o + i + 32, kr1);
}

// ---------------------------------------------------------------------------
// Prep 2: V transpose + split -> [b,h,d,L]
// ---------------------------------------------------------------------------
__global__ void vtrans_split(const float* __restrict__ qkuv,
    __nv_bfloat16* __restrict__ vth, __nv_bfloat16* __restrict__ vtl)
{
    __shared__ float ts[64][65];
    int b = blockIdx.z, h = blockIdx.y, l0 = blockIdx.x * 64;
    int tid = threadIdx.x;
    const float* vsrc = qkuv + (size_t)(b * Ll + l0) * NQKUV + 2 * Dd + h * HD;
    #pragma unroll
    for (int k = 0; k < 4; k++) {
        int c = tid + k * 256;
        int r = c >> 4, c4 = c & 15;
        float4 v = *(const float4*)(vsrc + (size_t)r * NQKUV + c4 * 4);
        ts[r][c4*4+0] = v.x; ts[r][c4*4+1] = v.y;
        ts[r][c4*4+2] = v.z; ts[r][c4*4+3] = v.w;
    }
    __syncthreads();
    size_t obase = ((size_t)((b * Hh + h) * HD)) * Ll + l0;
    #pragma unroll
    for (int k = 0; k < 4; k++) {
        int c = tid + k * 256;
        int d = c >> 4, j4 = c & 15;
        ushort4 ho, lo;
        unsigned short* hp = &ho.x; unsigned short* lp = &lo.x;
        #pragma unroll
        for (int j = 0; j < 4; j++) {
            float v = ts[j4*4 + j][d];
            __nv_bfloat16 hb = __float2bfloat16(v);
            hp[j] = __bfloat16_as_ushort(hb);
            lp[j] = __bfloat16_as_ushort(__float2bfloat16(v - __bfloat162float(hb)));
        }
        *(ushort4*)(vth + obase + (size_t)d * Ll + j4 * 4) = ho;
        *(ushort4*)(vtl + obase + (size_t)d * Ll + j4 * 4) = lo;
    }
}

// ---------------------------------------------------------------------------
// HMMA attention, register-resident S, mask staged in smem.
// Layout: [0, MQ_SZ) q-then-mask region; then double-buffered K/V.
// ---------------------------------------------------------------------------
#define ALD 72       // q/k smem pitch (bf16)
#define SLDV 136     // vT smem pitch (bf16)
#define MPITCH 132   // mask smem pitch (floats)
#define CM_FL (128 * MPITCH)            // cmask offset in floats
#define MQ_SZ 68096                     // 128*132*4 + 512
#define ST_BASE MQ_SZ
#define ST_SIZE 71680
#define ST_KH 0
#define ST_KL 18432
#define ST_VH 36864
#define ST_VL 54272
#define A_TOT (ST_BASE + 2 * ST_SIZE)   // 211456

__global__ __launch_bounds__(256) void attn_reg(
    const __nv_bfloat16* __restrict__ qh_g, const __nv_bfloat16* __restrict__ ql_g,
    const __nv_bfloat16* __restrict__ kh_g, const __nv_bfloat16* __restrict__ kl_g,
    const __nv_bfloat16* __restrict__ vth_g, const __nv_bfloat16* __restrict__ vtl_g,
    const float* __restrict__ attn_mask, const float* __restrict__ cmask,
    const float* __restrict__ cbias, float* __restrict__ out)
{
    extern __shared__ __align__(128) char sm[];
    const uint32_t smb = smem_u32(sm);
    const float* smf = (const float*)sm;
    const int tid = threadIdx.x;
    const int lane = tid & 31, wid = tid >> 5;
    const int b = blockIdx.z, h = blockIdx.y;
    const int l0 = blockIdx.x * 128;
    const size_t bh = (size_t)(b * Hh + h);
    const float cb = cbias[h];

    const __nv_bfloat16* qh_p = qh_g + (bh * Ll + l0) * HD;
    const __nv_bfloat16* ql_p = ql_g + (bh * Ll + l0) * HD;
    const __nv_bfloat16* kh_p = kh_g + bh * Ll * HD;
    const __nv_bfloat16* kl_p = kl_g + bh * Ll * HD;
    const __nv_bfloat16* vth_p = vth_g + bh * HD * Ll;
    const __nv_bfloat16* vtl_p = vtl_g + bh * HD * Ll;

    auto load_kv = [&](int m0k, int p) {
        uint32_t base = smb + ST_BASE + (uint32_t)p * ST_SIZE;
        #pragma unroll
        for (int i = 0; i < 4; i++) {           // k: 128 rows x 128B
            int c = tid + i * 256;
            int row = c >> 3, seg = c & 7;
            uint32_t d = (uint32_t)(row * 144 + seg * 16);
            size_t g = (size_t)(m0k + row) * HD + seg * 8;
            cp16(base + ST_KH + d, kh_p + g);
            cp16(base + ST_KL + d, kl_p + g);
        }
        #pragma unroll
        for (int i = 0; i < 4; i++) {           // vT: 64 rows x 256B
            int c = tid + i * 256;
            int row = c >> 4, seg = c & 15;
            uint32_t d = (uint32_t)(row * 272 + seg * 16);
            size_t g = (size_t)row * Ll + m0k + seg * 8;
            cp16(base + ST_VH + d, vth_p + g);
            cp16(base + ST_VL + d, vtl_p + g);
        }
        cp_commit();
    };

    auto load_mask = [&](int m0k) {
        #pragma unroll
        for (int i = 0; i < 16; i++) {          // 128 rows x 128 floats
            int c = tid + i * 256;
            int row = c >> 5, seg = c & 31;
            cp16(smb + (uint32_t)(row * MPITCH + seg * 4) * 4,
                 attn_mask + ((size_t)b * Ll + l0 + row) * Ll + m0k + seg * 4);
        }
        if (tid < 32)                           // cmask: 128 floats
            cp16(smb + (uint32_t)(CM_FL + tid * 4) * 4,
                 cmask + b * Ll + m0k + tid * 4);
        cp_commit();
    };

    // q tile -> smem (region later reused for mask)
    #pragma unroll
    for (int i = 0; i < 4; i++) {
        int c = tid + i * 256;
        int row = c >> 3, seg = c & 7;
        uint32_t d = (uint32_t)(row * 144 + seg * 16);
        size_t g = (size_t)row * HD + seg * 8;
        cp16(smb + d, qh_p + g);
        cp16(smb + 18432 + d, ql_p + g);
    }
    cp_commit();
    cp_wait_all();
    __syncthreads();

    // q fragments -> registers (once)
    const int brow = (lane & 7) + ((lane >> 4) << 3);
    const int bcol = ((lane >> 3) & 1) * 8;
    uint32_t qfh[4][4], qfl[4][4];
    {
        uint32_t roff = (uint32_t)((wid * 16 + (lane & 15)) * ALD) * 2;
        uint32_t coff = (uint32_t)((lane >> 4) * 8) * 2;
        #pragma unroll
        for (int ks = 0; ks < 4; ks++) {
            uint32_t off = roff + (uint32_t)(ks * 16) * 2 + coff;
            ldm_x4(qfh[ks], smb + off);
            ldm_x4(qfl[ks], smb + 18432 + off);
        }
    }
    __syncthreads();          // all frags hoisted before mask overwrites q
    load_kv(0, 0);

    float oacc[8][4];
    #pragma unroll
    for (int j = 0; j < 8; j++)
        #pragma unroll
        for (int q = 0; q < 4; q++) oacc[j][q] = 0.0f;

    const int rl = lane >> 2;
    const int rg0 = l0 + wid * 16 + rl;
    const int ct0 = (lane & 3) * 2;

    for (int t = 0; t < 16; t++) {
        const int p = t & 1;
        const int m0 = t * 128;
        cp_wait_all();             // kv(t) arrived
        __syncthreads();           // all warps done with SV(t-1) (mask + kv buffers free)
        load_mask(m0);                           // group 1 (oldest)
        if (t + 1 < 16) load_kv(m0 + 128, 1 - p); // group 2

        const uint32_t skh = smb + ST_BASE + (uint32_t)p * ST_SIZE + ST_KH;
        const uint32_t skl = skh + (ST_KL - ST_KH);
        const uint32_t svh = smb + ST_BASE + (uint32_t)p * ST_SIZE + ST_VH;
        const uint32_t svl = svh + (ST_VL - ST_VH);

        // ---- QK: S[16 rows][128 cols] in registers, 3-term ----
        float sacc[16][4];
        #pragma unroll
        for (int j = 0; j < 16; j++)
            #pragma unroll
            for (int q = 0; q < 4; q++) sacc[j][q] = 0.0f;

        #pragma unroll
        for (int ks = 0; ks < 4; ks++) {
            #pragma unroll
            for (int nbq = 0; nbq < 8; nbq++) {
                uint32_t kh4[4], kl4[4];
                uint32_t off = (uint32_t)((nbq * 16 + brow) * ALD + ks * 16 + bcol) * 2;
                ldm_x4(kh4, skh + off);
                ldm_x4(kl4, skl + off);
                #pragma unroll
                for (int half = 0; half < 2; half++) {
                    int j = nbq * 2 + half;
                    mma_bf16(sacc[j], qfh[ks], &kh4[half * 2]);
                    mma_bf16(sacc[j], qfh[ks], &kl4[half * 2]);
                    mma_bf16(sacc[j], qfl[ks], &kh4[half * 2]);
                }
            }
        }

        // mask(t) arrived (kv(t+1) may still be in flight)
        if (t + 1 < 16)
            asm volatile("cp.async.wait_group 1;" ::: "memory");
        else
            cp_wait_all();
        __syncthreads();          // mask visible to all warps

        // ---- SV with fused epilogue (mask/cmask from smem) ----
        #pragma unroll
        for (int s = 0; s < 8; s++) {
            uint32_t ah[4], al[4];
            #pragma unroll
            for (int e = 0; e < 2; e++) {
                int j = 2 * s + e;
                int cl = j * 8 + ct0;
                float2 cmv = *(const float2*)&smf[CM_FL + cl];
                int rloc = wid * 16 + rl;
                float2 mk0 = *(const float2*)&smf[rloc * MPITCH + cl];
                float2 mk1 = *(const float2*)&smf[(rloc + 8) * MPITCH + cl];
                float x0 = sacc[j][0] * 0.125f + cmv.x * cb;
                float x1 = sacc[j][1] * 0.125f + cmv.y * cb;
                float x2 = sacc[j][2] * 0.125f + cmv.x * cb;
                float x3 = sacc[j][3] * 0.125f + cmv.y * cb;
                float s0 = __fdividef(x0, 1.0f + __expf(-x0)) * mk0.x;
                float s1 = __fdividef(x1, 1.0f + __expf(-x1)) * mk0.y;
                float s2 = __fdividef(x2, 1.0f + __expf(-x2)) * mk1.x;
                float s3 = __fdividef(x3, 1.0f + __expf(-x3)) * mk1.y;
                split2(s0, s1, ah[e * 2 + 0], al[e * 2 + 0]);
                split2(s2, s3, ah[e * 2 + 1], al[e * 2 + 1]);
            }
            uint32_t fvh[4][4], fvl[4][4];
            #pragma unroll
            for (int dv = 0; dv < 4; dv++) {
                uint32_t off = (uint32_t)((dv * 16 + brow) * SLDV + s * 16 + bcol) * 2;
                ldm_x4(fvh[dv], svh + off);
                ldm_x4(fvl[dv], svl + off);
            }
            #pragma unroll
            for (int j = 0; j < 8; j++) {
                const uint32_t* bf = &fvh[j >> 1][(j & 1) * 2];
                const uint32_t* bl = &fvl[j >> 1][(j & 1) * 2];
                mma_bf16(oacc[j], ah, bf);
                mma_bf16(oacc[j], ah, bl);
                mma_bf16(oacc[j], al, bf);
            }
        }
    }

    // ---- write O: [b,h,l,d] fp32 ----
    #pragma unroll
    for (int j = 0; j < 8; j++) {
        int c = j * 8 + ct0;
        *(float2*)(out + (bh * Ll + rg0) * HD + c) = make_float2(oacc[j][0], oacc[j][1]);
        *(float2*)(out + (bh * Ll + rg0 + 8) * HD + c) = make_float2(oacc[j][2], oacc[j][3]);
    }
}

// ---------------------------------------------------------------------------
// LayerNorm(d) + u-gate -> split bf16 (B,L,D)
// ---------------------------------------------------------------------------
__global__ void ln_gate_kernel(
    const float* __restrict__ attn, const float* __restrict__ qkuv,
    const float* __restrict__ gamma, const float* __restrict__ beta,
    __nv_bfloat16* __restrict__ fh, __nv_bfloat16* __restrict__ fl)
{
    int warp = (blockIdx.x * blockDim.x + threadIdx.x) >> 5;
    int lane = threadIdx.x & 31;
    int l = warp & (Ll - 1);
    int h = (warp >> 11) & (Hh - 1);
    int b = warp >> 15;
    const float* row = attn + (size_t)warp * HD;
    float v0 = row[lane], v1 = row[lane + 32];
    float s = v0 + v1, sq = v0 * v0 + v1 * v1;
    #pragma unroll
    for (int o = 16; o > 0; o >>= 1) {
        s  += __shfl_xor_sync(0xFFFFFFFFu, s,  o);
        sq += __shfl_xor_sync(0xFFFFFFFFu, sq, o);
    }
    float mu = s * (1.0f / 64.0f);
    float var = sq * (1.0f / 64.0f) - mu * mu;
    float rstd = rsqrtf(var + 1e-5f);
    const float* ub = qkuv + ((size_t)(b * Ll + l)) * NQKUV + 3 * Dd + h * HD;
    size_t ob = ((size_t)(b * Ll + l)) * Dd + h * HD;
    float y0 = ((v0 - mu) * rstd * gamma[lane]      + beta[lane])      * ub[lane];
    float y1 = ((v1 - mu) * rstd * gamma[lane + 32] + beta[lane + 32]) * ub[lane + 32];
    split_store(fh, fl, ob + lane,      y0);
    split_store(fh, fl, ob + lane + 32, y1);
}

// ---------------------------------------------------------------------------
extern "C" void kernel_launch(void* const* d_in, const int* in_sizes, int n_in,
                              void* d_out, int out_size)
{
    const float *x = nullptr, *attn_mask = nullptr, *cmask = nullptr;
    const float *Wqkuv = nullptr, *Wout = nullptr;
    const float *gamma = nullptr, *beta = nullptr, *cbias = nullptr;
    for (int i = 0; i < n_in; i++) {
        const float* p = (const float*)d_in[i];
        switch (in_sizes[i]) {
            case MROWS * Dd:        x = p; break;
            case Bb * Ll * Ll:      attn_mask = p; break;
            case Bb * Ll:           cmask = p; break;
            case Dd * NQKUV:        Wqkuv = p; break;
            case Dd * Dd:           Wout = p; break;
            case HD:                if (!gamma) gamma = p; else beta = p; break;
            case Hh:                cbias = p; break;
            default: break;
        }
    }
    float* out = (float*)d_out;

    float *qkuv, *attn;
    __nv_bfloat16 *xh, *xl, *wth, *wtl, *woh, *wol, *fh, *fl;
    __nv_bfloat16 *qh, *ql, *kh, *kl, *vth, *vtl;
    cudaGetSymbolAddress((void**)&qkuv, g_qkuv);
    cudaGetSymbolAddress((void**)&attn, g_attn);
    cudaGetSymbolAddress((void**)&xh,  g_xh);
    cudaGetSymbolAddress((void**)&xl,  g_xl);
    cudaGetSymbolAddress((void**)&wth, g_wth);
    cudaGetSymbolAddress((void**)&wtl, g_wtl);
    cudaGetSymbolAddress((void**)&woh, g_woh);
    cudaGetSymbolAddress((void**)&wol, g_wol);
    cudaGetSymbolAddress((void**)&fh,  g_fh);
    cudaGetSymbolAddress((void**)&fl,  g_fl);
    cudaGetSymbolAddress((void**)&qh,  g_qh);
    cudaGetSymbolAddress((void**)&ql,  g_ql);
    cudaGetSymbolAddress((void**)&kh,  g_kh);
    cudaGetSymbolAddress((void**)&kl,  g_kl);
    cudaGetSymbolAddress((void**)&vth, g_vth);
    cudaGetSymbolAddress((void**)&vtl, g_vtl);

    cudaFuncSetAttribute(gemm_mma<true>,  cudaFuncAttributeMaxDynamicSharedMemorySize, SMEM_MMA);
    cudaFuncSetAttribute(gemm_mma<false>, cudaFuncAttributeMaxDynamicSharedMemorySize, SMEM_MMA);
    cudaFuncSetAttribute(attn_reg, cudaFuncAttributeMaxDynamicSharedMemorySize, A_TOT);

    // 1) splits
    split_rows<<<(MROWS * KDIM / 4) / 256, 256>>>(x, xh, xl);
    splitT<<<dim3(NQKUV / 32, KDIM / 32), dim3(32, 8)>>>(Wqkuv, wth, wtl, NQKUV);
    splitT<<<dim3(Dd / 32, KDIM / 32), dim3(32, 8)>>>(Wout, woh, wol, Dd);

    // 2) qkuv = silu(x @ Wqkuv)
    gemm_mma<true><<<dim3(NQKUV / 128, MROWS / 128), 256, SMEM_MMA>>>(
        xh, xl, wth, wtl, qkuv, NQKUV);

    // 3) prep attention operands
    rope_split_qk<<<(Bb * Ll * Hh * 32) / 256, 256>>>(qkuv, qh, ql, kh, kl);
    vtrans_split<<<dim3(Ll / 64, Hh, Bb), 256>>>(qkuv, vth, vtl);

    // 4) register-S HMMA attention with smem-staged mask
    attn_reg<<<dim3(Ll / 128, Hh, Bb), 256, A_TOT>>>(
        qh, ql, kh, kl, vth, vtl, attn_mask, cmask, cbias, attn);

    // 5) LayerNorm(d) + u-gate -> split bf16
    ln_gate_kernel<<<(Bb * Hh * Ll * 32) / 256, 256>>>(attn, qkuv, gamma, beta, fh, fl);

    // 6) out = flat @ Wout
    gemm_mma<false><<<dim3(Dd / 128, MROWS / 128), 256, SMEM_MMA>>>(
        fh, fl, woh, wol, out, Dd);
}